// round 7
// baseline (speedup 1.0000x reference)
#include <cuda_runtime.h>
#include <cuda_fp16.h>
#include <cstdint>

#define T_TOK 4096
#define DMODEL 768
#define HID 2048
#define NE 8
#define ALPHA 0.05f

#define AST 40          // A smem row stride in halves (80B, conflict-free for ldmatrix)
#define BST 72          // B smem row stride in halves (144B, conflict-free for ldmatrix.trans)
#define NC_UP (DMODEL / 32)   // 24 k-chunks
#define NC_DN (HID / 32)      // 64 k-chunks

// ---------------- scratch ----------------------------------------------------
__device__ int   g_expert[T_TOK];
__device__ float g_gate[T_TOK];
__device__ int   g_counts[NE];
__device__ int   g_off[NE + 1];
__device__ int   g_cursor[NE];
__device__ float g_ce[NE];
__device__ int   g_tok[T_TOK];
__device__ __align__(16) __half g_xg[(size_t)T_TOK * DMODEL];  // fp16 tokens, expert-sorted
__device__ __align__(16) __half g_h[(size_t)T_TOK * HID];      // fp16 silu(u)*v

// ---------------- helpers ----------------------------------------------------
__device__ __forceinline__ uint32_t smem_u32(const void* p) {
    uint32_t a;
    asm("{ .reg .u64 t; cvta.to.shared.u64 t, %1; cvt.u32.u64 %0, t; }" : "=r"(a) : "l"(p));
    return a;
}
__device__ __forceinline__ uint32_t pk(float a, float b) {
    __half2 h = __floats2half2_rn(a, b);
    return *reinterpret_cast<uint32_t*>(&h);
}
__device__ __forceinline__ void cpa16(uint32_t dst, const void* src, bool valid) {
    int sz = valid ? 16 : 0;
    asm volatile("cp.async.cg.shared.global [%0], [%1], 16, %2;\n"
                 :: "r"(dst), "l"(src), "r"(sz) : "memory");
}
#define CP_COMMIT() asm volatile("cp.async.commit_group;" ::: "memory")
#define CP_WAIT0()  asm volatile("cp.async.wait_group 0;" ::: "memory")

#define LDSM_X4(r0, r1, r2, r3, a)                                              \
    asm volatile("ldmatrix.sync.aligned.m8n8.x4.shared.b16 {%0,%1,%2,%3}, [%4];"\
                 : "=r"(r0), "=r"(r1), "=r"(r2), "=r"(r3) : "r"(a))
#define LDSM_X4T(r0, r1, r2, r3, a)                                             \
    asm volatile("ldmatrix.sync.aligned.m8n8.x4.trans.shared.b16 {%0,%1,%2,%3}, [%4];"\
                 : "=r"(r0), "=r"(r1), "=r"(r2), "=r"(r3) : "r"(a))

#define MMA16816(d, a, b0, b1)                                                  \
    asm volatile("mma.sync.aligned.m16n8k16.row.col.f32.f16.f16.f32 "           \
                 "{%0,%1,%2,%3},{%4,%5,%6,%7},{%8,%9},{%0,%1,%2,%3};"           \
                 : "+f"((d)[0]), "+f"((d)[1]), "+f"((d)[2]), "+f"((d)[3])       \
                 : "r"((a)[0]), "r"((a)[1]), "r"((a)[2]), "r"((a)[3]),          \
                   "r"(b0), "r"(b1))

// ---------------- small kernels ----------------------------------------------
__global__ void init_kernel() {
    int i = threadIdx.x;
    if (i < NE) { g_counts[i] = 0; g_ce[i] = 0.f; }
}

__global__ void gate_kernel(const float* __restrict__ x,
                            const float* __restrict__ wgw,
                            const float* __restrict__ wgb) {
    __shared__ float s_ce[NE];
    __shared__ int   s_cnt[NE];
    int tid = threadIdx.x;
    if (tid < NE) { s_ce[tid] = 0.f; s_cnt[tid] = 0; }
    __syncthreads();

    int warp = tid >> 5, lane = tid & 31;
    int t = blockIdx.x * 8 + warp;

    float acc[NE];
#pragma unroll
    for (int e = 0; e < NE; e++) acc[e] = 0.f;
    const float* xr = x + (size_t)t * DMODEL;
    for (int i = lane; i < DMODEL; i += 32) {
        float xv = xr[i];
#pragma unroll
        for (int e = 0; e < NE; e++) acc[e] += xv * wgw[e * DMODEL + i];
    }
#pragma unroll
    for (int e = 0; e < NE; e++)
#pragma unroll
        for (int o = 16; o > 0; o >>= 1) acc[e] += __shfl_xor_sync(0xFFFFFFFFu, acc[e], o);

    if (lane == 0) {
        float mx = -1e30f; int be = 0;
#pragma unroll
        for (int e = 0; e < NE; e++) {
            acc[e] += wgb[e];
            if (acc[e] > mx) { mx = acc[e]; be = e; }
        }
        float p[NE]; float s = 0.f;
#pragma unroll
        for (int e = 0; e < NE; e++) { p[e] = __expf(acc[e] - mx); s += p[e]; }
        float inv = 1.f / s;
#pragma unroll
        for (int e = 0; e < NE; e++) { p[e] *= inv; atomicAdd(&s_ce[e], p[e]); }
        g_expert[t] = be;
        g_gate[t]   = p[be];
        atomicAdd(&s_cnt[be], 1);
    }
    __syncthreads();
    if (tid < NE) { atomicAdd(&g_ce[tid], s_ce[tid]); atomicAdd(&g_counts[tid], s_cnt[tid]); }
}

__global__ void scan_kernel() {
    if (threadIdx.x == 0) {
        int s = 0;
        for (int e = 0; e < NE; e++) { g_off[e] = s; g_cursor[e] = s; s += g_counts[e]; }
        g_off[NE] = s;
    }
}

__global__ void gather_kernel(const float* __restrict__ x) {
    __shared__ int s_pos;
    int t = blockIdx.x;
    if (threadIdx.x == 0) {
        int e = g_expert[t];
        int pos = atomicAdd(&g_cursor[e], 1);
        g_tok[pos] = t;
        s_pos = pos;
    }
    __syncthreads();
    int pos = s_pos;
    const float4* src = (const float4*)(x + (size_t)t * DMODEL);
    __half2* dst = (__half2*)(g_xg + (size_t)pos * DMODEL);
    for (int i = threadIdx.x; i < DMODEL / 4; i += blockDim.x) {
        float4 v = src[i];
        dst[i * 2 + 0] = __floats2half2_rn(v.x, v.y);
        dst[i * 2 + 1] = __floats2half2_rn(v.z, v.w);
    }
}

// ---------------- up: H = silu(Xe@Wu)*(Xe@Wv), fp16 mma + ldmatrix ----------
// BM=128, BN=64, BK=32. 8 warps (4m x 2n), warp tile 32x32. 2 CTAs/SM.
__global__ __launch_bounds__(256, 2) void up_mma(const float* __restrict__ Wu,
                                                 const float* __restrict__ Wv) {
    int e    = blockIdx.z;
    int mEnd = g_off[e + 1];
    int m0   = g_off[e] + blockIdx.y * 128;
    if (m0 >= mEnd) return;
    int n0 = blockIdx.x * 64;

    __shared__ __align__(16) __half As[2][128 * AST];
    __shared__ __align__(16) __half Bu[2][32 * BST];
    __shared__ __align__(16) __half Bv[2][32 * BST];

    int tid = threadIdx.x, lane = tid & 31, wid = tid >> 5;
    int wm = wid & 3, wn = wid >> 2;
    int lg = lane >> 2, lt = lane & 3;

    uint32_t aA[2] = { smem_u32(As[0]), smem_u32(As[1]) };
    uint32_t aU[2] = { smem_u32(Bu[0]), smem_u32(Bu[1]) };
    uint32_t aV[2] = { smem_u32(Bv[0]), smem_u32(Bv[1]) };

    const float* WuE = Wu + (size_t)e * DMODEL * HID;
    const float* WvE = Wv + (size_t)e * DMODEL * HID;

    float au[2][4][4], av[2][4][4];
#pragma unroll
    for (int mt = 0; mt < 2; mt++)
#pragma unroll
        for (int nt = 0; nt < 4; nt++)
#pragma unroll
            for (int r = 0; r < 4; r++) { au[mt][nt][r] = 0.f; av[mt][nt][r] = 0.f; }

    int brow = tid >> 3, bcol = (tid & 7) * 8;     // B loader: k-row, 8 n-cols
    uint32_t pu2[4], pv2[4];                       // packed fp16x2 prefetch regs

    auto issueA = [&](int c, int st) {
#pragma unroll
        for (int q = 0; q < 2; q++) {
            int sidx = tid + q * 256;
            int row = sidx >> 2, sg = sidx & 3;
            int gm = m0 + row;
            bool v = gm < mEnd;
            uint32_t dst = aA[st] + (uint32_t)(row * AST + sg * 8) * 2;
            const __half* src = &g_xg[(size_t)(v ? gm : m0) * DMODEL + c * 32 + sg * 8];
            cpa16(dst, src, v);
        }
    };
    auto ldgB = [&](int c) {
        const float* ru = &WuE[(size_t)(c * 32 + brow) * HID + n0 + bcol];
        const float* rv = &WvE[(size_t)(c * 32 + brow) * HID + n0 + bcol];
        float4 a = *(const float4*)ru, b = *(const float4*)(ru + 4);
        pu2[0] = pk(a.x, a.y); pu2[1] = pk(a.z, a.w);
        pu2[2] = pk(b.x, b.y); pu2[3] = pk(b.z, b.w);
        float4 cdat = *(const float4*)rv, d = *(const float4*)(rv + 4);
        pv2[0] = pk(cdat.x, cdat.y); pv2[1] = pk(cdat.z, cdat.w);
        pv2[2] = pk(d.x, d.y);       pv2[3] = pk(d.z, d.w);
    };
    auto stsB = [&](int st) {
        *(uint4*)&Bu[st][brow * BST + bcol] = make_uint4(pu2[0], pu2[1], pu2[2], pu2[3]);
        *(uint4*)&Bv[st][brow * BST + bcol] = make_uint4(pv2[0], pv2[1], pv2[2], pv2[3]);
    };
    auto compute = [&](int st) {
#pragma unroll
        for (int s = 0; s < 2; s++) {
            int k0 = s * 16;
            uint32_t a[2][4];
#pragma unroll
            for (int mt = 0; mt < 2; mt++) {
                uint32_t ad = aA[st] + (uint32_t)(((wm * 32 + mt * 16 + (lane & 15)) * AST)
                                                  + k0 + (lane >> 4) * 8) * 2;
                LDSM_X4(a[mt][0], a[mt][1], a[mt][2], a[mt][3], ad);
            }
#pragma unroll
            for (int np = 0; np < 2; np++) {
                uint32_t boff = (uint32_t)(((k0 + (lane & 15)) * BST)
                                           + wn * 32 + np * 16 + (lane >> 4) * 8) * 2;
                uint32_t u0, u1, u2, u3, v0, v1, v2, v3;
                LDSM_X4T(u0, u1, u2, u3, aU[st] + boff);
                LDSM_X4T(v0, v1, v2, v3, aV[st] + boff);
#pragma unroll
                for (int mt = 0; mt < 2; mt++) {
                    MMA16816(au[mt][np * 2 + 0], a[mt], u0, u1);
                    MMA16816(au[mt][np * 2 + 1], a[mt], u2, u3);
                    MMA16816(av[mt][np * 2 + 0], a[mt], v0, v1);
                    MMA16816(av[mt][np * 2 + 1], a[mt], v2, v3);
                }
            }
        }
    };

    issueA(0, 0); ldgB(0); stsB(0);
    CP_COMMIT(); CP_WAIT0(); __syncthreads();

    for (int c = 0; c < NC_UP; c++) {
        int buf = c & 1;
        bool pf = (c + 1) < NC_UP;
        if (pf) { issueA(c + 1, buf ^ 1); ldgB(c + 1); }
        compute(buf);
        if (pf) stsB(buf ^ 1);
        CP_COMMIT(); CP_WAIT0(); __syncthreads();
    }

    // epilogue: silu(u)*v -> g_h (fp16)
#pragma unroll
    for (int mt = 0; mt < 2; mt++) {
#pragma unroll
        for (int nt = 0; nt < 4; nt++) {
            int row0 = m0 + wm * 32 + mt * 16 + lg;
            int col  = n0 + wn * 32 + nt * 8 + lt * 2;
            if (row0 < mEnd) {
                float u0 = au[mt][nt][0], u1 = au[mt][nt][1];
                float h0 = u0 / (1.f + __expf(-u0)) * av[mt][nt][0];
                float h1 = u1 / (1.f + __expf(-u1)) * av[mt][nt][1];
                *(__half2*)&g_h[(size_t)row0 * HID + col] = __floats2half2_rn(h0, h1);
            }
            int row1 = row0 + 8;
            if (row1 < mEnd) {
                float u2 = au[mt][nt][2], u3 = au[mt][nt][3];
                float h2 = u2 / (1.f + __expf(-u2)) * av[mt][nt][2];
                float h3 = u3 / (1.f + __expf(-u3)) * av[mt][nt][3];
                *(__half2*)&g_h[(size_t)row1 * HID + col] = __floats2half2_rn(h2, h3);
            }
        }
    }
}

// ---------------- down: y[token] = gate * (H @ Wd[e]) ------------------------
__global__ __launch_bounds__(256, 2) void dn_mma(const float* __restrict__ Wd,
                                                 float* __restrict__ out) {
    int e    = blockIdx.z;
    int mEnd = g_off[e + 1];
    int m0   = g_off[e] + blockIdx.y * 128;
    if (m0 >= mEnd) return;
    int n0 = blockIdx.x * 64;

    __shared__ __align__(16) __half As[2][128 * AST];
    __shared__ __align__(16) __half Bs[2][32 * BST];

    int tid = threadIdx.x, lane = tid & 31, wid = tid >> 5;
    int wm = wid & 3, wn = wid >> 2;
    int lg = lane >> 2, lt = lane & 3;

    uint32_t aA[2] = { smem_u32(As[0]), smem_u32(As[1]) };
    uint32_t aB[2] = { smem_u32(Bs[0]), smem_u32(Bs[1]) };

    const float* WdE = Wd + (size_t)e * HID * DMODEL;

    float acc[2][4][4];
#pragma unroll
    for (int mt = 0; mt < 2; mt++)
#pragma unroll
        for (int nt = 0; nt < 4; nt++)
#pragma unroll
            for (int r = 0; r < 4; r++) acc[mt][nt][r] = 0.f;

    int brow = tid >> 3, bcol = (tid & 7) * 8;
    uint32_t pb2[4];

    auto issueA = [&](int c, int st) {
#pragma unroll
        for (int q = 0; q < 2; q++) {
            int sidx = tid + q * 256;
            int row = sidx >> 2, sg = sidx & 3;
            int gm = m0 + row;
            bool v = gm < mEnd;
            uint32_t dst = aA[st] + (uint32_t)(row * AST + sg * 8) * 2;
            const __half* src = &g_h[(size_t)(v ? gm : m0) * HID + c * 32 + sg * 8];
            cpa16(dst, src, v);
        }
    };
    auto ldgB = [&](int c) {
        const float* rb = &WdE[(size_t)(c * 32 + brow) * DMODEL + n0 + bcol];
        float4 a = *(const float4*)rb, b = *(const float4*)(rb + 4);
        pb2[0] = pk(a.x, a.y); pb2[1] = pk(a.z, a.w);
        pb2[2] = pk(b.x, b.y); pb2[3] = pk(b.z, b.w);
    };
    auto stsB = [&](int st) {
        *(uint4*)&Bs[st][brow * BST + bcol] = make_uint4(pb2[0], pb2[1], pb2[2], pb2[3]);
    };
    auto compute = [&](int st) {
#pragma unroll
        for (int s = 0; s < 2; s++) {
            int k0 = s * 16;
            uint32_t a[2][4];
#pragma unroll
            for (int mt = 0; mt < 2; mt++) {
                uint32_t ad = aA[st] + (uint32_t)(((wm * 32 + mt * 16 + (lane & 15)) * AST)
                                                  + k0 + (lane >> 4) * 8) * 2;
                LDSM_X4(a[mt][0], a[mt][1], a[mt][2], a[mt][3], ad);
            }
#pragma unroll
            for (int np = 0; np < 2; np++) {
                uint32_t boff = (uint32_t)(((k0 + (lane & 15)) * BST)
                                           + wn * 32 + np * 16 + (lane >> 4) * 8) * 2;
                uint32_t b0, b1, b2, b3;
                LDSM_X4T(b0, b1, b2, b3, aB[st] + boff);
#pragma unroll
                for (int mt = 0; mt < 2; mt++) {
                    MMA16816(acc[mt][np * 2 + 0], a[mt], b0, b1);
                    MMA16816(acc[mt][np * 2 + 1], a[mt], b2, b3);
                }
            }
        }
    };

    issueA(0, 0); ldgB(0); stsB(0);
    CP_COMMIT(); CP_WAIT0(); __syncthreads();

    for (int c = 0; c < NC_DN; c++) {
        int buf = c & 1;
        bool pf = (c + 1) < NC_DN;
        if (pf) { issueA(c + 1, buf ^ 1); ldgB(c + 1); }
        compute(buf);
        if (pf) stsB(buf ^ 1);
        CP_COMMIT(); CP_WAIT0(); __syncthreads();
    }

#pragma unroll
    for (int mt = 0; mt < 2; mt++) {
#pragma unroll
        for (int nt = 0; nt < 4; nt++) {
            int row0 = m0 + wm * 32 + mt * 16 + lg;
            int col  = n0 + wn * 32 + nt * 8 + lt * 2;
            if (row0 < mEnd) {
                int token = g_tok[row0];
                float gate = g_gate[token];
                *(float2*)&out[(size_t)token * DMODEL + col] =
                    make_float2(acc[mt][nt][0] * gate, acc[mt][nt][1] * gate);
            }
            int row1 = row0 + 8;
            if (row1 < mEnd) {
                int token = g_tok[row1];
                float gate = g_gate[token];
                *(float2*)&out[(size_t)token * DMODEL + col] =
                    make_float2(acc[mt][nt][2] * gate, acc[mt][nt][3] * gate);
            }
        }
    }
}

// ---------------- aux --------------------------------------------------------
__global__ void aux_kernel(float* __restrict__ out) {
    float s = 0.f;
    for (int e = 0; e < NE; e++) {
        float me = (float)g_counts[e] / (float)T_TOK;
        float ce = g_ce[e] / (float)T_TOK;
        s += me * ce;
    }
    out[(size_t)T_TOK * DMODEL] = ALPHA * NE * s;
}

// ---------------- launch -----------------------------------------------------
extern "C" void kernel_launch(void* const* d_in, const int* in_sizes, int n_in,
                              void* d_out, int out_size) {
    const float* x   = (const float*)d_in[0];
    const float* wgw = (const float*)d_in[1];
    const float* wgb = (const float*)d_in[2];
    const float* Wu  = (const float*)d_in[3];
    const float* Wv  = (const float*)d_in[4];
    const float* Wd  = (const float*)d_in[5];
    float* out = (float*)d_out;

    init_kernel<<<1, 32>>>();
    gate_kernel<<<T_TOK / 8, 256>>>(x, wgw, wgb);
    scan_kernel<<<1, 1>>>();
    gather_kernel<<<T_TOK, 192>>>(x);
    up_mma<<<dim3(HID / 64, T_TOK / 128, NE), 256>>>(Wu, Wv);
    dn_mma<<<dim3(DMODEL / 64, T_TOK / 128, NE), 256>>>(Wd, out);
    aux_kernel<<<1, 1>>>(out);
}

// round 8
// speedup vs baseline: 1.2462x; 1.2462x over previous
#include <cuda_runtime.h>
#include <cuda_fp16.h>
#include <cstdint>

#define T_TOK 4096
#define DMODEL 768
#define HID 2048
#define NE 8
#define ALPHA 0.05f

#define AST 40                 // A smem row stride (halves): 80B, ldmatrix conflict-free
#define BST 72                 // B smem row stride (halves): 144B, ldmatrix.trans conflict-free
#define NC_UP (DMODEL / 32)    // 24
#define NC_DN (HID / 32)       // 64
#define A_TILE (128 * AST)     // halves per A stage
#define B_TILE (32 * BST)      // halves per B stage
#define UP_SMEM ((3 * (A_TILE + 2 * B_TILE)) * 2)   // 58368 B
#define DN_SMEM ((3 * (A_TILE + B_TILE)) * 2)       // 44544 B

// ---------------- scratch ----------------------------------------------------
__device__ int   g_expert[T_TOK];
__device__ float g_gate[T_TOK];
__device__ int   g_counts[NE];
__device__ int   g_off[NE + 1];
__device__ int   g_cursor[NE];
__device__ float g_ce[NE];
__device__ int   g_tok[T_TOK];
__device__ __align__(16) __half g_xg[(size_t)T_TOK * DMODEL];
__device__ __align__(16) __half g_h[(size_t)T_TOK * HID];
__device__ __align__(16) __half g_wu16[(size_t)NE * DMODEL * HID];
__device__ __align__(16) __half g_wv16[(size_t)NE * DMODEL * HID];
__device__ __align__(16) __half g_wd16[(size_t)NE * HID * DMODEL];

// ---------------- helpers ----------------------------------------------------
__device__ __forceinline__ uint32_t smem_u32(const void* p) {
    uint32_t a;
    asm("{ .reg .u64 t; cvta.to.shared.u64 t, %1; cvt.u32.u64 %0, t; }" : "=r"(a) : "l"(p));
    return a;
}
__device__ __forceinline__ uint32_t pk(float a, float b) {
    __half2 h = __floats2half2_rn(a, b);
    return *reinterpret_cast<uint32_t*>(&h);
}
__device__ __forceinline__ void cpa16(uint32_t dst, const void* src, bool valid) {
    int sz = valid ? 16 : 0;
    asm volatile("cp.async.cg.shared.global [%0], [%1], 16, %2;\n"
                 :: "r"(dst), "l"(src), "r"(sz) : "memory");
}
#define CP_COMMIT() asm volatile("cp.async.commit_group;" ::: "memory")
#define CP_WAIT1()  asm volatile("cp.async.wait_group 1;" ::: "memory")

#define LDSM_X4(r0, r1, r2, r3, a)                                              \
    asm volatile("ldmatrix.sync.aligned.m8n8.x4.shared.b16 {%0,%1,%2,%3}, [%4];"\
                 : "=r"(r0), "=r"(r1), "=r"(r2), "=r"(r3) : "r"(a))
#define LDSM_X4T(r0, r1, r2, r3, a)                                             \
    asm volatile("ldmatrix.sync.aligned.m8n8.x4.trans.shared.b16 {%0,%1,%2,%3}, [%4];"\
                 : "=r"(r0), "=r"(r1), "=r"(r2), "=r"(r3) : "r"(a))

#define MMA16816(d, a, b0, b1)                                                  \
    asm volatile("mma.sync.aligned.m16n8k16.row.col.f32.f16.f16.f32 "           \
                 "{%0,%1,%2,%3},{%4,%5,%6,%7},{%8,%9},{%0,%1,%2,%3};"           \
                 : "+f"((d)[0]), "+f"((d)[1]), "+f"((d)[2]), "+f"((d)[3])       \
                 : "r"((a)[0]), "r"((a)[1]), "r"((a)[2]), "r"((a)[3]),          \
                   "r"(b0), "r"(b1))

// ---------------- weight convert: fp32 -> fp16 -------------------------------
__global__ void convert_kernel(const float* __restrict__ Wu,
                               const float* __restrict__ Wv,
                               const float* __restrict__ Wd) {
    const size_t n4 = (size_t)NE * DMODEL * HID / 4;
    size_t stride = (size_t)gridDim.x * blockDim.x;
    for (size_t i = blockIdx.x * (size_t)blockDim.x + threadIdx.x; i < n4; i += stride) {
        float4 a = ((const float4*)Wu)[i];
        ((uint2*)g_wu16)[i] = make_uint2(pk(a.x, a.y), pk(a.z, a.w));
        float4 b = ((const float4*)Wv)[i];
        ((uint2*)g_wv16)[i] = make_uint2(pk(b.x, b.y), pk(b.z, b.w));
        float4 c = ((const float4*)Wd)[i];
        ((uint2*)g_wd16)[i] = make_uint2(pk(c.x, c.y), pk(c.z, c.w));
    }
}

// ---------------- small kernels ----------------------------------------------
__global__ void init_kernel() {
    int i = threadIdx.x;
    if (i < NE) { g_counts[i] = 0; g_ce[i] = 0.f; }
}

__global__ void gate_kernel(const float* __restrict__ x,
                            const float* __restrict__ wgw,
                            const float* __restrict__ wgb) {
    __shared__ float s_ce[NE];
    __shared__ int   s_cnt[NE];
    int tid = threadIdx.x;
    if (tid < NE) { s_ce[tid] = 0.f; s_cnt[tid] = 0; }
    __syncthreads();

    int warp = tid >> 5, lane = tid & 31;
    int t = blockIdx.x * 8 + warp;

    float acc[NE];
#pragma unroll
    for (int e = 0; e < NE; e++) acc[e] = 0.f;
    const float* xr = x + (size_t)t * DMODEL;
    for (int i = lane; i < DMODEL; i += 32) {
        float xv = xr[i];
#pragma unroll
        for (int e = 0; e < NE; e++) acc[e] += xv * wgw[e * DMODEL + i];
    }
#pragma unroll
    for (int e = 0; e < NE; e++)
#pragma unroll
        for (int o = 16; o > 0; o >>= 1) acc[e] += __shfl_xor_sync(0xFFFFFFFFu, acc[e], o);

    if (lane == 0) {
        float mx = -1e30f; int be = 0;
#pragma unroll
        for (int e = 0; e < NE; e++) {
            acc[e] += wgb[e];
            if (acc[e] > mx) { mx = acc[e]; be = e; }
        }
        float p[NE]; float s = 0.f;
#pragma unroll
        for (int e = 0; e < NE; e++) { p[e] = __expf(acc[e] - mx); s += p[e]; }
        float inv = 1.f / s;
#pragma unroll
        for (int e = 0; e < NE; e++) { p[e] *= inv; atomicAdd(&s_ce[e], p[e]); }
        g_expert[t] = be;
        g_gate[t]   = p[be];
        atomicAdd(&s_cnt[be], 1);
    }
    __syncthreads();
    if (tid < NE) { atomicAdd(&g_ce[tid], s_ce[tid]); atomicAdd(&g_counts[tid], s_cnt[tid]); }
}

__global__ void scan_kernel() {
    if (threadIdx.x == 0) {
        int s = 0;
        for (int e = 0; e < NE; e++) { g_off[e] = s; g_cursor[e] = s; s += g_counts[e]; }
        g_off[NE] = s;
    }
}

__global__ void gather_kernel(const float* __restrict__ x) {
    __shared__ int s_pos;
    int t = blockIdx.x;
    if (threadIdx.x == 0) {
        int e = g_expert[t];
        int pos = atomicAdd(&g_cursor[e], 1);
        g_tok[pos] = t;
        s_pos = pos;
    }
    __syncthreads();
    int pos = s_pos;
    const float4* src = (const float4*)(x + (size_t)t * DMODEL);
    __half2* dst = (__half2*)(g_xg + (size_t)pos * DMODEL);
    for (int i = threadIdx.x; i < DMODEL / 4; i += blockDim.x) {
        float4 v = src[i];
        dst[i * 2 + 0] = __floats2half2_rn(v.x, v.y);
        dst[i * 2 + 1] = __floats2half2_rn(v.z, v.w);
    }
}

// ---------------- up: H = silu(Xe@Wu)*(Xe@Wv) --------------------------------
// BM=128, BN=64, BK=32; 8 warps (4m x 2n) warp tile 32x32; 3-stage cp.async.
__global__ __launch_bounds__(256, 2) void up_mma(float* __restrict__ dummy) {
    int e    = blockIdx.z;
    int mEnd = g_off[e + 1];
    int m0   = g_off[e] + blockIdx.y * 128;
    if (m0 >= mEnd) return;
    int n0 = blockIdx.x * 64;

    extern __shared__ __align__(16) __half smem[];
    __half* As = smem;                 // 3 stages x A_TILE
    __half* Bu = smem + 3 * A_TILE;    // 3 stages x B_TILE
    __half* Bv = Bu + 3 * B_TILE;

    int tid = threadIdx.x, lane = tid & 31, wid = tid >> 5;
    int wm = wid & 3, wn = wid >> 2;
    int lg = lane >> 2, lt = lane & 3;

    uint32_t baseA = smem_u32(As), baseU = smem_u32(Bu), baseV = smem_u32(Bv);

    const __half* WuE = g_wu16 + (size_t)e * DMODEL * HID;
    const __half* WvE = g_wv16 + (size_t)e * DMODEL * HID;

    float au[2][4][4], av[2][4][4];
#pragma unroll
    for (int mt = 0; mt < 2; mt++)
#pragma unroll
        for (int nt = 0; nt < 4; nt++)
#pragma unroll
            for (int r = 0; r < 4; r++) { au[mt][nt][r] = 0.f; av[mt][nt][r] = 0.f; }

    int arow = tid >> 2, asg = tid & 3;    // A: 512 segs, 2/thread
    int brow = tid >> 3, bsg = tid & 7;    // B: 256 segs/tile, 1/thread/tile

    auto issue = [&](int c, int st) {
        uint32_t dA = baseA + (uint32_t)(st * A_TILE) * 2;
        uint32_t dU = baseU + (uint32_t)(st * B_TILE) * 2;
        uint32_t dV = baseV + (uint32_t)(st * B_TILE) * 2;
#pragma unroll
        for (int q = 0; q < 2; q++) {
            int row = arow + q * 64;
            int gm = m0 + row;
            bool v = gm < mEnd;
            cpa16(dA + (uint32_t)(row * AST + asg * 8) * 2,
                  &g_xg[(size_t)(v ? gm : m0) * DMODEL + c * 32 + asg * 8], v);
        }
        size_t boff = (size_t)(c * 32 + brow) * HID + n0 + bsg * 8;
        cpa16(dU + (uint32_t)(brow * BST + bsg * 8) * 2, WuE + boff, true);
        cpa16(dV + (uint32_t)(brow * BST + bsg * 8) * 2, WvE + boff, true);
    };
    auto compute = [&](int st) {
        uint32_t sA = baseA + (uint32_t)(st * A_TILE) * 2;
        uint32_t sU = baseU + (uint32_t)(st * B_TILE) * 2;
        uint32_t sV = baseV + (uint32_t)(st * B_TILE) * 2;
#pragma unroll
        for (int s = 0; s < 2; s++) {
            int k0 = s * 16;
            uint32_t a[2][4];
#pragma unroll
            for (int mt = 0; mt < 2; mt++) {
                uint32_t ad = sA + (uint32_t)(((wm * 32 + mt * 16 + (lane & 15)) * AST)
                                              + k0 + (lane >> 4) * 8) * 2;
                LDSM_X4(a[mt][0], a[mt][1], a[mt][2], a[mt][3], ad);
            }
#pragma unroll
            for (int np = 0; np < 2; np++) {
                uint32_t boff = (uint32_t)(((k0 + (lane & 15)) * BST)
                                           + wn * 32 + np * 16 + (lane >> 4) * 8) * 2;
                uint32_t u0, u1, u2, u3, v0, v1, v2, v3;
                LDSM_X4T(u0, u1, u2, u3, sU + boff);
                LDSM_X4T(v0, v1, v2, v3, sV + boff);
#pragma unroll
                for (int mt = 0; mt < 2; mt++) {
                    MMA16816(au[mt][np * 2 + 0], a[mt], u0, u1);
                    MMA16816(au[mt][np * 2 + 1], a[mt], u2, u3);
                    MMA16816(av[mt][np * 2 + 0], a[mt], v0, v1);
                    MMA16816(av[mt][np * 2 + 1], a[mt], v2, v3);
                }
            }
        }
    };

    issue(0, 0); CP_COMMIT();
    issue(1, 1); CP_COMMIT();

    for (int c = 0; c < NC_UP; c++) {
        CP_WAIT1();
        __syncthreads();
        if (c + 2 < NC_UP) issue(c + 2, (c + 2) % 3);
        CP_COMMIT();
        compute(c % 3);
    }

    // epilogue: silu(u)*v -> g_h (fp16)
#pragma unroll
    for (int mt = 0; mt < 2; mt++) {
#pragma unroll
        for (int nt = 0; nt < 4; nt++) {
            int row0 = m0 + wm * 32 + mt * 16 + lg;
            int col  = n0 + wn * 32 + nt * 8 + lt * 2;
            if (row0 < mEnd) {
                float u0 = au[mt][nt][0], u1 = au[mt][nt][1];
                float h0 = u0 / (1.f + __expf(-u0)) * av[mt][nt][0];
                float h1 = u1 / (1.f + __expf(-u1)) * av[mt][nt][1];
                *(__half2*)&g_h[(size_t)row0 * HID + col] = __floats2half2_rn(h0, h1);
            }
            int row1 = row0 + 8;
            if (row1 < mEnd) {
                float u2 = au[mt][nt][2], u3 = au[mt][nt][3];
                float h2 = u2 / (1.f + __expf(-u2)) * av[mt][nt][2];
                float h3 = u3 / (1.f + __expf(-u3)) * av[mt][nt][3];
                *(__half2*)&g_h[(size_t)row1 * HID + col] = __floats2half2_rn(h2, h3);
            }
        }
    }
}

// ---------------- down: y[token] = gate * (H @ Wd[e]) ------------------------
__global__ __launch_bounds__(256, 2) void dn_mma(float* __restrict__ out) {
    int e    = blockIdx.z;
    int mEnd = g_off[e + 1];
    int m0   = g_off[e] + blockIdx.y * 128;
    if (m0 >= mEnd) return;
    int n0 = blockIdx.x * 64;

    extern __shared__ __align__(16) __half smem[];
    __half* As = smem;
    __half* Bs = smem + 3 * A_TILE;

    int tid = threadIdx.x, lane = tid & 31, wid = tid >> 5;
    int wm = wid & 3, wn = wid >> 2;
    int lg = lane >> 2, lt = lane & 3;

    uint32_t baseA = smem_u32(As), baseB = smem_u32(Bs);

    const __half* WdE = g_wd16 + (size_t)e * HID * DMODEL;

    float acc[2][4][4];
#pragma unroll
    for (int mt = 0; mt < 2; mt++)
#pragma unroll
        for (int nt = 0; nt < 4; nt++)
#pragma unroll
            for (int r = 0; r < 4; r++) acc[mt][nt][r] = 0.f;

    int arow = tid >> 2, asg = tid & 3;
    int brow = tid >> 3, bsg = tid & 7;

    auto issue = [&](int c, int st) {
        uint32_t dA = baseA + (uint32_t)(st * A_TILE) * 2;
        uint32_t dB = baseB + (uint32_t)(st * B_TILE) * 2;
#pragma unroll
        for (int q = 0; q < 2; q++) {
            int row = arow + q * 64;
            int gm = m0 + row;
            bool v = gm < mEnd;
            cpa16(dA + (uint32_t)(row * AST + asg * 8) * 2,
                  &g_h[(size_t)(v ? gm : m0) * HID + c * 32 + asg * 8], v);
        }
        cpa16(dB + (uint32_t)(brow * BST + bsg * 8) * 2,
              WdE + (size_t)(c * 32 + brow) * DMODEL + n0 + bsg * 8, true);
    };
    auto compute = [&](int st) {
        uint32_t sA = baseA + (uint32_t)(st * A_TILE) * 2;
        uint32_t sB = baseB + (uint32_t)(st * B_TILE) * 2;
#pragma unroll
        for (int s = 0; s < 2; s++) {
            int k0 = s * 16;
            uint32_t a[2][4];
#pragma unroll
            for (int mt = 0; mt < 2; mt++) {
                uint32_t ad = sA + (uint32_t)(((wm * 32 + mt * 16 + (lane & 15)) * AST)
                                              + k0 + (lane >> 4) * 8) * 2;
                LDSM_X4(a[mt][0], a[mt][1], a[mt][2], a[mt][3], ad);
            }
#pragma unroll
            for (int np = 0; np < 2; np++) {
                uint32_t boff = (uint32_t)(((k0 + (lane & 15)) * BST)
                                           + wn * 32 + np * 16 + (lane >> 4) * 8) * 2;
                uint32_t b0, b1, b2, b3;
                LDSM_X4T(b0, b1, b2, b3, sB + boff);
#pragma unroll
                for (int mt = 0; mt < 2; mt++) {
                    MMA16816(acc[mt][np * 2 + 0], a[mt], b0, b1);
                    MMA16816(acc[mt][np * 2 + 1], a[mt], b2, b3);
                }
            }
        }
    };

    issue(0, 0); CP_COMMIT();
    issue(1, 1); CP_COMMIT();

    for (int c = 0; c < NC_DN; c++) {
        CP_WAIT1();
        __syncthreads();
        if (c + 2 < NC_DN) issue(c + 2, (c + 2) % 3);
        CP_COMMIT();
        compute(c % 3);
    }

#pragma unroll
    for (int mt = 0; mt < 2; mt++) {
#pragma unroll
        for (int nt = 0; nt < 4; nt++) {
            int row0 = m0 + wm * 32 + mt * 16 + lg;
            int col  = n0 + wn * 32 + nt * 8 + lt * 2;
            if (row0 < mEnd) {
                int token = g_tok[row0];
                float gate = g_gate[token];
                *(float2*)&out[(size_t)token * DMODEL + col] =
                    make_float2(acc[mt][nt][0] * gate, acc[mt][nt][1] * gate);
            }
            int row1 = row0 + 8;
            if (row1 < mEnd) {
                int token = g_tok[row1];
                float gate = g_gate[token];
                *(float2*)&out[(size_t)token * DMODEL + col] =
                    make_float2(acc[mt][nt][2] * gate, acc[mt][nt][3] * gate);
            }
        }
    }
}

// ---------------- aux --------------------------------------------------------
__global__ void aux_kernel(float* __restrict__ out) {
    float s = 0.f;
    for (int e = 0; e < NE; e++) {
        float me = (float)g_counts[e] / (float)T_TOK;
        float ce = g_ce[e] / (float)T_TOK;
        s += me * ce;
    }
    out[(size_t)T_TOK * DMODEL] = ALPHA * NE * s;
}

// ---------------- launch -----------------------------------------------------
extern "C" void kernel_launch(void* const* d_in, const int* in_sizes, int n_in,
                              void* d_out, int out_size) {
    const float* x   = (const float*)d_in[0];
    const float* wgw = (const float*)d_in[1];
    const float* wgb = (const float*)d_in[2];
    const float* Wu  = (const float*)d_in[3];
    const float* Wv  = (const float*)d_in[4];
    const float* Wd  = (const float*)d_in[5];
    float* out = (float*)d_out;

    cudaFuncSetAttribute(up_mma, cudaFuncAttributeMaxDynamicSharedMemorySize, UP_SMEM);
    cudaFuncSetAttribute(dn_mma, cudaFuncAttributeMaxDynamicSharedMemorySize, DN_SMEM);

    init_kernel<<<1, 32>>>();
    convert_kernel<<<1184, 256>>>(Wu, Wv, Wd);
    gate_kernel<<<T_TOK / 8, 256>>>(x, wgw, wgb);
    scan_kernel<<<1, 1>>>();
    gather_kernel<<<T_TOK, 192>>>(x);
    up_mma<<<dim3(HID / 64, T_TOK / 128, NE), 256, UP_SMEM>>>(nullptr);
    dn_mma<<<dim3(DMODEL / 64, T_TOK / 128, NE), 256, DN_SMEM>>>(out);
    aux_kernel<<<1, 1>>>(out);
}

// round 9
// speedup vs baseline: 1.2916x; 1.0364x over previous
#include <cuda_runtime.h>
#include <cuda_fp16.h>
#include <cstdint>

#define T_TOK 4096
#define DMODEL 768
#define HID 2048
#define NE 8
#define ALPHA 0.05f

#define AST 40                 // A smem row stride (halves): 80B, ldmatrix conflict-free
#define BST 72                 // B smem row stride (halves): 144B, ldmatrix.trans conflict-free
#define NC_UP (DMODEL / 32)    // 24
#define NC_DN (HID / 32)       // 64
#define A_TILE (128 * AST)
#define B_TILE (32 * BST)
#define UP_SMEM ((3 * (A_TILE + 2 * B_TILE)) * 2)   // 58368 B
#define DN_SMEM ((3 * (A_TILE + B_TILE)) * 2)       // 44544 B

#define GATE_BLOCKS 512
#define CONVUV_BLOCKS 1536
#define GATHER_BLOCKS T_TOK
#define CONVD_BLOCKS 2048

// ---------------- scratch ----------------------------------------------------
__device__ int   g_expert[T_TOK];
__device__ float g_gate[T_TOK];
__device__ int   g_counts[NE];
__device__ int   g_off[NE + 1];
__device__ int   g_cursor[NE];
__device__ float g_ce[NE];
__device__ int   g_tok[T_TOK];
__device__ int   g_done;
__device__ __align__(16) __half g_xg[(size_t)T_TOK * DMODEL];
__device__ __align__(16) __half g_h[(size_t)T_TOK * HID];
__device__ __align__(16) __half g_wu16[(size_t)NE * DMODEL * HID];
__device__ __align__(16) __half g_wv16[(size_t)NE * DMODEL * HID];
__device__ __align__(16) __half g_wd16[(size_t)NE * HID * DMODEL];

// ---------------- helpers ----------------------------------------------------
__device__ __forceinline__ uint32_t smem_u32(const void* p) {
    uint32_t a;
    asm("{ .reg .u64 t; cvta.to.shared.u64 t, %1; cvt.u32.u64 %0, t; }" : "=r"(a) : "l"(p));
    return a;
}
__device__ __forceinline__ uint32_t pk(float a, float b) {
    __half2 h = __floats2half2_rn(a, b);
    return *reinterpret_cast<uint32_t*>(&h);
}
__device__ __forceinline__ void cpa16(uint32_t dst, const void* src, bool valid) {
    int sz = valid ? 16 : 0;
    asm volatile("cp.async.cg.shared.global [%0], [%1], 16, %2;\n"
                 :: "r"(dst), "l"(src), "r"(sz) : "memory");
}
#define CP_COMMIT() asm volatile("cp.async.commit_group;" ::: "memory")
#define CP_WAIT1()  asm volatile("cp.async.wait_group 1;" ::: "memory")

#define LDSM_X4(r0, r1, r2, r3, a)                                              \
    asm volatile("ldmatrix.sync.aligned.m8n8.x4.shared.b16 {%0,%1,%2,%3}, [%4];"\
                 : "=r"(r0), "=r"(r1), "=r"(r2), "=r"(r3) : "r"(a))
#define LDSM_X4T(r0, r1, r2, r3, a)                                             \
    asm volatile("ldmatrix.sync.aligned.m8n8.x4.trans.shared.b16 {%0,%1,%2,%3}, [%4];"\
                 : "=r"(r0), "=r"(r1), "=r"(r2), "=r"(r3) : "r"(a))

#define MMA16816(d, a, b0, b1)                                                  \
    asm volatile("mma.sync.aligned.m16n8k16.row.col.f32.f16.f16.f32 "           \
                 "{%0,%1,%2,%3},{%4,%5,%6,%7},{%8,%9},{%0,%1,%2,%3};"           \
                 : "+f"((d)[0]), "+f"((d)[1]), "+f"((d)[2]), "+f"((d)[3])       \
                 : "r"((a)[0]), "r"((a)[1]), "r"((a)[2]), "r"((a)[3]),          \
                   "r"(b0), "r"(b1))

// ---------------- init -------------------------------------------------------
__global__ void init_kernel() {
    int i = threadIdx.x;
    if (i < NE) { g_counts[i] = 0; g_ce[i] = 0.f; }
    if (i == 0) g_done = 0;
}

// ---------------- gate (+ Wu/Wv convert in extra blocks, + inline scan) ------
__global__ void gate_kernel(const float* __restrict__ x,
                            const float* __restrict__ wgw,
                            const float* __restrict__ wgb,
                            const float* __restrict__ Wu,
                            const float* __restrict__ Wv) {
    int tid = threadIdx.x;

    if (blockIdx.x >= GATE_BLOCKS) {
        // ---- convert Wu, Wv fp32 -> fp16 ----
        const size_t n4 = (size_t)NE * DMODEL * HID / 4;
        size_t i0 = (size_t)(blockIdx.x - GATE_BLOCKS) * blockDim.x + tid;
        size_t stride = (size_t)CONVUV_BLOCKS * blockDim.x;
        for (size_t i = i0; i < n4; i += stride) {
            float4 a = ((const float4*)Wu)[i];
            ((uint2*)g_wu16)[i] = make_uint2(pk(a.x, a.y), pk(a.z, a.w));
            float4 b = ((const float4*)Wv)[i];
            ((uint2*)g_wv16)[i] = make_uint2(pk(b.x, b.y), pk(b.z, b.w));
        }
        return;
    }

    __shared__ float s_ce[NE];
    __shared__ int   s_cnt[NE];
    if (tid < NE) { s_ce[tid] = 0.f; s_cnt[tid] = 0; }
    __syncthreads();

    int warp = tid >> 5, lane = tid & 31;
    int t = blockIdx.x * 8 + warp;

    float acc[NE];
#pragma unroll
    for (int e = 0; e < NE; e++) acc[e] = 0.f;
    const float* xr = x + (size_t)t * DMODEL;
    for (int i = lane; i < DMODEL; i += 32) {
        float xv = xr[i];
#pragma unroll
        for (int e = 0; e < NE; e++) acc[e] += xv * wgw[e * DMODEL + i];
    }
#pragma unroll
    for (int e = 0; e < NE; e++)
#pragma unroll
        for (int o = 16; o > 0; o >>= 1) acc[e] += __shfl_xor_sync(0xFFFFFFFFu, acc[e], o);

    if (lane == 0) {
        float mx = -1e30f; int be = 0;
#pragma unroll
        for (int e = 0; e < NE; e++) {
            acc[e] += wgb[e];
            if (acc[e] > mx) { mx = acc[e]; be = e; }
        }
        float p[NE]; float s = 0.f;
#pragma unroll
        for (int e = 0; e < NE; e++) { p[e] = __expf(acc[e] - mx); s += p[e]; }
        float inv = 1.f / s;
#pragma unroll
        for (int e = 0; e < NE; e++) { p[e] *= inv; atomicAdd(&s_ce[e], p[e]); }
        g_expert[t] = be;
        g_gate[t]   = p[be];
        atomicAdd(&s_cnt[be], 1);
    }
    __syncthreads();
    if (tid < NE) { atomicAdd(&g_ce[tid], s_ce[tid]); atomicAdd(&g_counts[tid], s_cnt[tid]); }

    // ---- last gate block performs the 8-way exclusive scan inline ----
    if (tid == 0) {
        __threadfence();
        int prev = atomicAdd(&g_done, 1);
        if (prev == GATE_BLOCKS - 1) {
            int s = 0;
            for (int e = 0; e < NE; e++) {
                int cnt = atomicAdd(&g_counts[e], 0);
                g_off[e] = s; g_cursor[e] = s; s += cnt;
            }
            g_off[NE] = s;
            __threadfence();
        }
    }
}

// ---------------- gather (+ Wd convert in extra blocks) ----------------------
__global__ void gather_kernel(const float* __restrict__ x,
                              const float* __restrict__ Wd) {
    if (blockIdx.x >= GATHER_BLOCKS) {
        const size_t n4 = (size_t)NE * HID * DMODEL / 4;
        size_t i0 = (size_t)(blockIdx.x - GATHER_BLOCKS) * blockDim.x + threadIdx.x;
        size_t stride = (size_t)CONVD_BLOCKS * blockDim.x;
        for (size_t i = i0; i < n4; i += stride) {
            float4 c = ((const float4*)Wd)[i];
            ((uint2*)g_wd16)[i] = make_uint2(pk(c.x, c.y), pk(c.z, c.w));
        }
        return;
    }

    __shared__ int s_pos;
    int t = blockIdx.x;
    if (threadIdx.x == 0) {
        int e = g_expert[t];
        int pos = atomicAdd(&g_cursor[e], 1);
        g_tok[pos] = t;
        s_pos = pos;
    }
    __syncthreads();
    int pos = s_pos;
    const float4* src = (const float4*)(x + (size_t)t * DMODEL);
    __half2* dst = (__half2*)(g_xg + (size_t)pos * DMODEL);
    for (int i = threadIdx.x; i < DMODEL / 4; i += blockDim.x) {
        float4 v = src[i];
        dst[i * 2 + 0] = __floats2half2_rn(v.x, v.y);
        dst[i * 2 + 1] = __floats2half2_rn(v.z, v.w);
    }
}

// ---------------- up: H = silu(Xe@Wu)*(Xe@Wv) --------------------------------
__global__ __launch_bounds__(256, 2) void up_mma(float* __restrict__ dummy) {
    int e    = blockIdx.z;
    int mEnd = g_off[e + 1];
    int m0   = g_off[e] + blockIdx.y * 128;
    if (m0 >= mEnd) return;
    int n0 = blockIdx.x * 64;

    extern __shared__ __align__(16) __half smem[];
    __half* As = smem;
    __half* Bu = smem + 3 * A_TILE;
    __half* Bv = Bu + 3 * B_TILE;

    int tid = threadIdx.x, lane = tid & 31, wid = tid >> 5;
    int wm = wid & 3, wn = wid >> 2;
    int lg = lane >> 2, lt = lane & 3;

    uint32_t baseA = smem_u32(As), baseU = smem_u32(Bu), baseV = smem_u32(Bv);

    const __half* WuE = g_wu16 + (size_t)e * DMODEL * HID;
    const __half* WvE = g_wv16 + (size_t)e * DMODEL * HID;

    float au[2][4][4], av[2][4][4];
#pragma unroll
    for (int mt = 0; mt < 2; mt++)
#pragma unroll
        for (int nt = 0; nt < 4; nt++)
#pragma unroll
            for (int r = 0; r < 4; r++) { au[mt][nt][r] = 0.f; av[mt][nt][r] = 0.f; }

    int arow = tid >> 2, asg = tid & 3;
    int brow = tid >> 3, bsg = tid & 7;

    auto issue = [&](int c, int st) {
        uint32_t dA = baseA + (uint32_t)(st * A_TILE) * 2;
        uint32_t dU = baseU + (uint32_t)(st * B_TILE) * 2;
        uint32_t dV = baseV + (uint32_t)(st * B_TILE) * 2;
#pragma unroll
        for (int q = 0; q < 2; q++) {
            int row = arow + q * 64;
            int gm = m0 + row;
            bool v = gm < mEnd;
            cpa16(dA + (uint32_t)(row * AST + asg * 8) * 2,
                  &g_xg[(size_t)(v ? gm : m0) * DMODEL + c * 32 + asg * 8], v);
        }
        size_t boff = (size_t)(c * 32 + brow) * HID + n0 + bsg * 8;
        cpa16(dU + (uint32_t)(brow * BST + bsg * 8) * 2, WuE + boff, true);
        cpa16(dV + (uint32_t)(brow * BST + bsg * 8) * 2, WvE + boff, true);
    };
    auto compute = [&](int st) {
        uint32_t sA = baseA + (uint32_t)(st * A_TILE) * 2;
        uint32_t sU = baseU + (uint32_t)(st * B_TILE) * 2;
        uint32_t sV = baseV + (uint32_t)(st * B_TILE) * 2;
#pragma unroll
        for (int s = 0; s < 2; s++) {
            int k0 = s * 16;
            uint32_t a[2][4];
#pragma unroll
            for (int mt = 0; mt < 2; mt++) {
                uint32_t ad = sA + (uint32_t)(((wm * 32 + mt * 16 + (lane & 15)) * AST)
                                              + k0 + (lane >> 4) * 8) * 2;
                LDSM_X4(a[mt][0], a[mt][1], a[mt][2], a[mt][3], ad);
            }
#pragma unroll
            for (int np = 0; np < 2; np++) {
                uint32_t boff = (uint32_t)(((k0 + (lane & 15)) * BST)
                                           + wn * 32 + np * 16 + (lane >> 4) * 8) * 2;
                uint32_t u0, u1, u2, u3, v0, v1, v2, v3;
                LDSM_X4T(u0, u1, u2, u3, sU + boff);
                LDSM_X4T(v0, v1, v2, v3, sV + boff);
#pragma unroll
                for (int mt = 0; mt < 2; mt++) {
                    MMA16816(au[mt][np * 2 + 0], a[mt], u0, u1);
                    MMA16816(au[mt][np * 2 + 1], a[mt], u2, u3);
                    MMA16816(av[mt][np * 2 + 0], a[mt], v0, v1);
                    MMA16816(av[mt][np * 2 + 1], a[mt], v2, v3);
                }
            }
        }
    };

    issue(0, 0); CP_COMMIT();
    issue(1, 1); CP_COMMIT();

    for (int c = 0; c < NC_UP; c++) {
        CP_WAIT1();
        __syncthreads();
        if (c + 2 < NC_UP) issue(c + 2, (c + 2) % 3);
        CP_COMMIT();
        compute(c % 3);
    }

#pragma unroll
    for (int mt = 0; mt < 2; mt++) {
#pragma unroll
        for (int nt = 0; nt < 4; nt++) {
            int row0 = m0 + wm * 32 + mt * 16 + lg;
            int col  = n0 + wn * 32 + nt * 8 + lt * 2;
            if (row0 < mEnd) {
                float u0 = au[mt][nt][0], u1 = au[mt][nt][1];
                float h0 = u0 / (1.f + __expf(-u0)) * av[mt][nt][0];
                float h1 = u1 / (1.f + __expf(-u1)) * av[mt][nt][1];
                *(__half2*)&g_h[(size_t)row0 * HID + col] = __floats2half2_rn(h0, h1);
            }
            int row1 = row0 + 8;
            if (row1 < mEnd) {
                float u2 = au[mt][nt][2], u3 = au[mt][nt][3];
                float h2 = u2 / (1.f + __expf(-u2)) * av[mt][nt][2];
                float h3 = u3 / (1.f + __expf(-u3)) * av[mt][nt][3];
                *(__half2*)&g_h[(size_t)row1 * HID + col] = __floats2half2_rn(h2, h3);
            }
        }
    }
}

// ---------------- down: y[token] = gate * (H @ Wd[e]) ------------------------
__global__ __launch_bounds__(256, 2) void dn_mma(float* __restrict__ out) {
    int e    = blockIdx.z;
    int mEnd = g_off[e + 1];
    int m0   = g_off[e] + blockIdx.y * 128;
    if (m0 >= mEnd) return;
    int n0 = blockIdx.x * 64;

    extern __shared__ __align__(16) __half smem[];
    __half* As = smem;
    __half* Bs = smem + 3 * A_TILE;

    int tid = threadIdx.x, lane = tid & 31, wid = tid >> 5;
    int wm = wid & 3, wn = wid >> 2;
    int lg = lane >> 2, lt = lane & 3;

    uint32_t baseA = smem_u32(As), baseB = smem_u32(Bs);

    const __half* WdE = g_wd16 + (size_t)e * HID * DMODEL;

    float acc[2][4][4];
#pragma unroll
    for (int mt = 0; mt < 2; mt++)
#pragma unroll
        for (int nt = 0; nt < 4; nt++)
#pragma unroll
            for (int r = 0; r < 4; r++) acc[mt][nt][r] = 0.f;

    int arow = tid >> 2, asg = tid & 3;
    int brow = tid >> 3, bsg = tid & 7;

    auto issue = [&](int c, int st) {
        uint32_t dA = baseA + (uint32_t)(st * A_TILE) * 2;
        uint32_t dB = baseB + (uint32_t)(st * B_TILE) * 2;
#pragma unroll
        for (int q = 0; q < 2; q++) {
            int row = arow + q * 64;
            int gm = m0 + row;
            bool v = gm < mEnd;
            cpa16(dA + (uint32_t)(row * AST + asg * 8) * 2,
                  &g_h[(size_t)(v ? gm : m0) * HID + c * 32 + asg * 8], v);
        }
        cpa16(dB + (uint32_t)(brow * BST + bsg * 8) * 2,
              WdE + (size_t)(c * 32 + brow) * DMODEL + n0 + bsg * 8, true);
    };
    auto compute = [&](int st) {
        uint32_t sA = baseA + (uint32_t)(st * A_TILE) * 2;
        uint32_t sB = baseB + (uint32_t)(st * B_TILE) * 2;
#pragma unroll
        for (int s = 0; s < 2; s++) {
            int k0 = s * 16;
            uint32_t a[2][4];
#pragma unroll
            for (int mt = 0; mt < 2; mt++) {
                uint32_t ad = sA + (uint32_t)(((wm * 32 + mt * 16 + (lane & 15)) * AST)
                                              + k0 + (lane >> 4) * 8) * 2;
                LDSM_X4(a[mt][0], a[mt][1], a[mt][2], a[mt][3], ad);
            }
#pragma unroll
            for (int np = 0; np < 2; np++) {
                uint32_t boff = (uint32_t)(((k0 + (lane & 15)) * BST)
                                           + wn * 32 + np * 16 + (lane >> 4) * 8) * 2;
                uint32_t b0, b1, b2, b3;
                LDSM_X4T(b0, b1, b2, b3, sB + boff);
#pragma unroll
                for (int mt = 0; mt < 2; mt++) {
                    MMA16816(acc[mt][np * 2 + 0], a[mt], b0, b1);
                    MMA16816(acc[mt][np * 2 + 1], a[mt], b2, b3);
                }
            }
        }
    };

    issue(0, 0); CP_COMMIT();
    issue(1, 1); CP_COMMIT();

    for (int c = 0; c < NC_DN; c++) {
        CP_WAIT1();
        __syncthreads();
        if (c + 2 < NC_DN) issue(c + 2, (c + 2) % 3);
        CP_COMMIT();
        compute(c % 3);
    }

#pragma unroll
    for (int mt = 0; mt < 2; mt++) {
#pragma unroll
        for (int nt = 0; nt < 4; nt++) {
            int row0 = m0 + wm * 32 + mt * 16 + lg;
            int col  = n0 + wn * 32 + nt * 8 + lt * 2;
            if (row0 < mEnd) {
                int token = g_tok[row0];
                float gate = g_gate[token];
                *(float2*)&out[(size_t)token * DMODEL + col] =
                    make_float2(acc[mt][nt][0] * gate, acc[mt][nt][1] * gate);
            }
            int row1 = row0 + 8;
            if (row1 < mEnd) {
                int token = g_tok[row1];
                float gate = g_gate[token];
                *(float2*)&out[(size_t)token * DMODEL + col] =
                    make_float2(acc[mt][nt][2] * gate, acc[mt][nt][3] * gate);
            }
        }
    }
}

// ---------------- aux --------------------------------------------------------
__global__ void aux_kernel(float* __restrict__ out) {
    float s = 0.f;
    for (int e = 0; e < NE; e++) {
        float me = (float)g_counts[e] / (float)T_TOK;
        float ce = g_ce[e] / (float)T_TOK;
        s += me * ce;
    }
    out[(size_t)T_TOK * DMODEL] = ALPHA * NE * s;
}

// ---------------- launch -----------------------------------------------------
extern "C" void kernel_launch(void* const* d_in, const int* in_sizes, int n_in,
                              void* d_out, int out_size) {
    const float* x   = (const float*)d_in[0];
    const float* wgw = (const float*)d_in[1];
    const float* wgb = (const float*)d_in[2];
    const float* Wu  = (const float*)d_in[3];
    const float* Wv  = (const float*)d_in[4];
    const float* Wd  = (const float*)d_in[5];
    float* out = (float*)d_out;

    cudaFuncSetAttribute(up_mma, cudaFuncAttributeMaxDynamicSharedMemorySize, UP_SMEM);
    cudaFuncSetAttribute(dn_mma, cudaFuncAttributeMaxDynamicSharedMemorySize, DN_SMEM);

    init_kernel<<<1, 32>>>();
    gate_kernel<<<GATE_BLOCKS + CONVUV_BLOCKS, 256>>>(x, wgw, wgb, Wu, Wv);
    gather_kernel<<<GATHER_BLOCKS + CONVD_BLOCKS, 192>>>(x, Wd);
    up_mma<<<dim3(HID / 64, T_TOK / 128, NE), 256, UP_SMEM>>>(nullptr);
    dn_mma<<<dim3(DMODEL / 64, T_TOK / 128, NE), 256, DN_SMEM>>>(out);
    aux_kernel<<<1, 1>>>(out);
}

// round 10
// speedup vs baseline: 1.3528x; 1.0474x over previous
#include <cuda_runtime.h>
#include <cuda_fp16.h>
#include <cstdint>

#define T_TOK 4096
#define DMODEL 768
#define HID 2048
#define NE 8
#define ALPHA 0.05f

#define AST 40                 // A smem row stride (halves)
#define BST 72                 // up B smem row stride (halves)
#define BSTD 136               // dn B smem row stride (halves), BN=128 + pad
#define NC_UP (DMODEL / 32)    // 24
#define NC_DN (HID / 32)       // 64
#define A_TILE (128 * AST)
#define B_TILE (32 * BST)
#define BD_TILE (32 * BSTD)
#define UP_SMEM ((3 * (A_TILE + 2 * B_TILE)) * 2)    // 58368 B
#define DN_SMEM ((3 * (A_TILE + BD_TILE)) * 2)       // 56832 B

#define GATE_BLOCKS 512
#define CONVUV_BLOCKS 1536
#define GATHER_BLOCKS T_TOK
#define CONVD_BLOCKS 2048

// ---------------- scratch ----------------------------------------------------
__device__ int   g_expert[T_TOK];
__device__ float g_gate[T_TOK];
__device__ int   g_counts[NE];
__device__ int   g_off[NE + 1];
__device__ int   g_cursor[NE];
__device__ float g_ce[NE];
__device__ int   g_tok[T_TOK];
__device__ int   g_done;
__device__ __align__(16) __half g_xg[(size_t)T_TOK * DMODEL];
__device__ __align__(16) __half g_h[(size_t)T_TOK * HID];
__device__ __align__(16) __half g_wu16[(size_t)NE * DMODEL * HID];
__device__ __align__(16) __half g_wv16[(size_t)NE * DMODEL * HID];
__device__ __align__(16) __half g_wd16[(size_t)NE * HID * DMODEL];

// ---------------- helpers ----------------------------------------------------
__device__ __forceinline__ uint32_t smem_u32(const void* p) {
    uint32_t a;
    asm("{ .reg .u64 t; cvta.to.shared.u64 t, %1; cvt.u32.u64 %0, t; }" : "=r"(a) : "l"(p));
    return a;
}
__device__ __forceinline__ uint32_t pk(float a, float b) {
    __half2 h = __floats2half2_rn(a, b);
    return *reinterpret_cast<uint32_t*>(&h);
}
__device__ __forceinline__ void cpa16(uint32_t dst, const void* src, bool valid) {
    int sz = valid ? 16 : 0;
    asm volatile("cp.async.cg.shared.global [%0], [%1], 16, %2;\n"
                 :: "r"(dst), "l"(src), "r"(sz) : "memory");
}
#define CP_COMMIT() asm volatile("cp.async.commit_group;" ::: "memory")
#define CP_WAIT1()  asm volatile("cp.async.wait_group 1;" ::: "memory")

#define LDSM_X4(r0, r1, r2, r3, a)                                              \
    asm volatile("ldmatrix.sync.aligned.m8n8.x4.shared.b16 {%0,%1,%2,%3}, [%4];"\
                 : "=r"(r0), "=r"(r1), "=r"(r2), "=r"(r3) : "r"(a))
#define LDSM_X4T(r0, r1, r2, r3, a)                                             \
    asm volatile("ldmatrix.sync.aligned.m8n8.x4.trans.shared.b16 {%0,%1,%2,%3}, [%4];"\
                 : "=r"(r0), "=r"(r1), "=r"(r2), "=r"(r3) : "r"(a))

#define MMA16816(d, a, b0, b1)                                                  \
    asm volatile("mma.sync.aligned.m16n8k16.row.col.f32.f16.f16.f32 "           \
                 "{%0,%1,%2,%3},{%4,%5,%6,%7},{%8,%9},{%0,%1,%2,%3};"           \
                 : "+f"((d)[0]), "+f"((d)[1]), "+f"((d)[2]), "+f"((d)[3])       \
                 : "r"((a)[0]), "r"((a)[1]), "r"((a)[2]), "r"((a)[3]),          \
                   "r"(b0), "r"(b1))

// ---------------- init -------------------------------------------------------
__global__ void init_kernel() {
    int i = threadIdx.x;
    if (i < NE) { g_counts[i] = 0; g_ce[i] = 0.f; }
    if (i == 0) g_done = 0;
}

// ---------------- gate (+ Wu/Wv convert in extra blocks, + inline scan) ------
__global__ void gate_kernel(const float* __restrict__ x,
                            const float* __restrict__ wgw,
                            const float* __restrict__ wgb,
                            const float* __restrict__ Wu,
                            const float* __restrict__ Wv) {
    int tid = threadIdx.x;

    if (blockIdx.x >= GATE_BLOCKS) {
        const size_t n4 = (size_t)NE * DMODEL * HID / 4;
        size_t i0 = (size_t)(blockIdx.x - GATE_BLOCKS) * blockDim.x + tid;
        size_t stride = (size_t)CONVUV_BLOCKS * blockDim.x;
        for (size_t i = i0; i < n4; i += stride) {
            float4 a = ((const float4*)Wu)[i];
            ((uint2*)g_wu16)[i] = make_uint2(pk(a.x, a.y), pk(a.z, a.w));
            float4 b = ((const float4*)Wv)[i];
            ((uint2*)g_wv16)[i] = make_uint2(pk(b.x, b.y), pk(b.z, b.w));
        }
        return;
    }

    __shared__ float s_ce[NE];
    __shared__ int   s_cnt[NE];
    if (tid < NE) { s_ce[tid] = 0.f; s_cnt[tid] = 0; }
    __syncthreads();

    int warp = tid >> 5, lane = tid & 31;
    int t = blockIdx.x * 8 + warp;

    float acc[NE];
#pragma unroll
    for (int e = 0; e < NE; e++) acc[e] = 0.f;
    const float* xr = x + (size_t)t * DMODEL;
    for (int i = lane; i < DMODEL; i += 32) {
        float xv = xr[i];
#pragma unroll
        for (int e = 0; e < NE; e++) acc[e] += xv * wgw[e * DMODEL + i];
    }
#pragma unroll
    for (int e = 0; e < NE; e++)
#pragma unroll
        for (int o = 16; o > 0; o >>= 1) acc[e] += __shfl_xor_sync(0xFFFFFFFFu, acc[e], o);

    if (lane == 0) {
        float mx = -1e30f; int be = 0;
#pragma unroll
        for (int e = 0; e < NE; e++) {
            acc[e] += wgb[e];
            if (acc[e] > mx) { mx = acc[e]; be = e; }
        }
        float p[NE]; float s = 0.f;
#pragma unroll
        for (int e = 0; e < NE; e++) { p[e] = __expf(acc[e] - mx); s += p[e]; }
        float inv = 1.f / s;
#pragma unroll
        for (int e = 0; e < NE; e++) { p[e] *= inv; atomicAdd(&s_ce[e], p[e]); }
        g_expert[t] = be;
        g_gate[t]   = p[be];
        atomicAdd(&s_cnt[be], 1);
    }
    __syncthreads();
    if (tid < NE) { atomicAdd(&g_ce[tid], s_ce[tid]); atomicAdd(&g_counts[tid], s_cnt[tid]); }

    if (tid == 0) {
        __threadfence();
        int prev = atomicAdd(&g_done, 1);
        if (prev == GATE_BLOCKS - 1) {
            int s = 0;
            for (int e = 0; e < NE; e++) {
                int cnt = atomicAdd(&g_counts[e], 0);
                g_off[e] = s; g_cursor[e] = s; s += cnt;
            }
            g_off[NE] = s;
            __threadfence();
        }
    }
}

// ---------------- gather (+ Wd convert in extra blocks) ----------------------
__global__ void gather_kernel(const float* __restrict__ x,
                              const float* __restrict__ Wd) {
    if (blockIdx.x >= GATHER_BLOCKS) {
        const size_t n4 = (size_t)NE * HID * DMODEL / 4;
        size_t i0 = (size_t)(blockIdx.x - GATHER_BLOCKS) * blockDim.x + threadIdx.x;
        size_t stride = (size_t)CONVD_BLOCKS * blockDim.x;
        for (size_t i = i0; i < n4; i += stride) {
            float4 c = ((const float4*)Wd)[i];
            ((uint2*)g_wd16)[i] = make_uint2(pk(c.x, c.y), pk(c.z, c.w));
        }
        return;
    }

    __shared__ int s_pos;
    int t = blockIdx.x;
    if (threadIdx.x == 0) {
        int e = g_expert[t];
        int pos = atomicAdd(&g_cursor[e], 1);
        g_tok[pos] = t;
        s_pos = pos;
    }
    __syncthreads();
    int pos = s_pos;
    const float4* src = (const float4*)(x + (size_t)t * DMODEL);
    __half2* dst = (__half2*)(g_xg + (size_t)pos * DMODEL);
    for (int i = threadIdx.x; i < DMODEL / 4; i += blockDim.x) {
        float4 v = src[i];
        dst[i * 2 + 0] = __floats2half2_rn(v.x, v.y);
        dst[i * 2 + 1] = __floats2half2_rn(v.z, v.w);
    }
}

// ---------------- up: H = silu(Xe@Wu)*(Xe@Wv) — unchanged from R9 ------------
__global__ __launch_bounds__(256, 2) void up_mma(float* __restrict__ dummy) {
    int e    = blockIdx.z;
    int mEnd = g_off[e + 1];
    int m0   = g_off[e] + blockIdx.y * 128;
    if (m0 >= mEnd) return;
    int n0 = blockIdx.x * 64;

    extern __shared__ __align__(16) __half smem[];
    __half* As = smem;
    __half* Bu = smem + 3 * A_TILE;
    __half* Bv = Bu + 3 * B_TILE;

    int tid = threadIdx.x, lane = tid & 31, wid = tid >> 5;
    int wm = wid & 3, wn = wid >> 2;
    int lg = lane >> 2, lt = lane & 3;

    uint32_t baseA = smem_u32(As), baseU = smem_u32(Bu), baseV = smem_u32(Bv);

    const __half* WuE = g_wu16 + (size_t)e * DMODEL * HID;
    const __half* WvE = g_wv16 + (size_t)e * DMODEL * HID;

    float au[2][4][4], av[2][4][4];
#pragma unroll
    for (int mt = 0; mt < 2; mt++)
#pragma unroll
        for (int nt = 0; nt < 4; nt++)
#pragma unroll
            for (int r = 0; r < 4; r++) { au[mt][nt][r] = 0.f; av[mt][nt][r] = 0.f; }

    int arow = tid >> 2, asg = tid & 3;
    int brow = tid >> 3, bsg = tid & 7;

    auto issue = [&](int c, int st) {
        uint32_t dA = baseA + (uint32_t)(st * A_TILE) * 2;
        uint32_t dU = baseU + (uint32_t)(st * B_TILE) * 2;
        uint32_t dV = baseV + (uint32_t)(st * B_TILE) * 2;
#pragma unroll
        for (int q = 0; q < 2; q++) {
            int row = arow + q * 64;
            int gm = m0 + row;
            bool v = gm < mEnd;
            cpa16(dA + (uint32_t)(row * AST + asg * 8) * 2,
                  &g_xg[(size_t)(v ? gm : m0) * DMODEL + c * 32 + asg * 8], v);
        }
        size_t boff = (size_t)(c * 32 + brow) * HID + n0 + bsg * 8;
        cpa16(dU + (uint32_t)(brow * BST + bsg * 8) * 2, WuE + boff, true);
        cpa16(dV + (uint32_t)(brow * BST + bsg * 8) * 2, WvE + boff, true);
    };
    auto compute = [&](int st) {
        uint32_t sA = baseA + (uint32_t)(st * A_TILE) * 2;
        uint32_t sU = baseU + (uint32_t)(st * B_TILE) * 2;
        uint32_t sV = baseV + (uint32_t)(st * B_TILE) * 2;
#pragma unroll
        for (int s = 0; s < 2; s++) {
            int k0 = s * 16;
            uint32_t a[2][4];
#pragma unroll
            for (int mt = 0; mt < 2; mt++) {
                uint32_t ad = sA + (uint32_t)(((wm * 32 + mt * 16 + (lane & 15)) * AST)
                                              + k0 + (lane >> 4) * 8) * 2;
                LDSM_X4(a[mt][0], a[mt][1], a[mt][2], a[mt][3], ad);
            }
#pragma unroll
            for (int np = 0; np < 2; np++) {
                uint32_t boff = (uint32_t)(((k0 + (lane & 15)) * BST)
                                           + wn * 32 + np * 16 + (lane >> 4) * 8) * 2;
                uint32_t u0, u1, u2, u3, v0, v1, v2, v3;
                LDSM_X4T(u0, u1, u2, u3, sU + boff);
                LDSM_X4T(v0, v1, v2, v3, sV + boff);
#pragma unroll
                for (int mt = 0; mt < 2; mt++) {
                    MMA16816(au[mt][np * 2 + 0], a[mt], u0, u1);
                    MMA16816(au[mt][np * 2 + 1], a[mt], u2, u3);
                    MMA16816(av[mt][np * 2 + 0], a[mt], v0, v1);
                    MMA16816(av[mt][np * 2 + 1], a[mt], v2, v3);
                }
            }
        }
    };

    issue(0, 0); CP_COMMIT();
    issue(1, 1); CP_COMMIT();

    for (int c = 0; c < NC_UP; c++) {
        CP_WAIT1();
        __syncthreads();
        if (c + 2 < NC_UP) issue(c + 2, (c + 2) % 3);
        CP_COMMIT();
        compute(c % 3);
    }

#pragma unroll
    for (int mt = 0; mt < 2; mt++) {
#pragma unroll
        for (int nt = 0; nt < 4; nt++) {
            int row0 = m0 + wm * 32 + mt * 16 + lg;
            int col  = n0 + wn * 32 + nt * 8 + lt * 2;
            if (row0 < mEnd) {
                float u0 = au[mt][nt][0], u1 = au[mt][nt][1];
                float h0 = u0 / (1.f + __expf(-u0)) * av[mt][nt][0];
                float h1 = u1 / (1.f + __expf(-u1)) * av[mt][nt][1];
                *(__half2*)&g_h[(size_t)row0 * HID + col] = __floats2half2_rn(h0, h1);
            }
            int row1 = row0 + 8;
            if (row1 < mEnd) {
                float u2 = au[mt][nt][2], u3 = au[mt][nt][3];
                float h2 = u2 / (1.f + __expf(-u2)) * av[mt][nt][2];
                float h3 = u3 / (1.f + __expf(-u3)) * av[mt][nt][3];
                *(__half2*)&g_h[(size_t)row1 * HID + col] = __floats2half2_rn(h2, h3);
            }
        }
    }
}

// ---------------- down: BN=128, warp tile 32x64 ------------------------------
__global__ __launch_bounds__(256, 2) void dn_mma(float* __restrict__ out) {
    int e    = blockIdx.z;
    int mEnd = g_off[e + 1];
    int m0   = g_off[e] + blockIdx.y * 128;
    if (m0 >= mEnd) return;
    int n0 = blockIdx.x * 128;

    extern __shared__ __align__(16) __half smem[];
    __half* As = smem;
    __half* Bs = smem + 3 * A_TILE;

    int tid = threadIdx.x, lane = tid & 31, wid = tid >> 5;
    int wm = wid & 3, wn = wid >> 2;
    int lg = lane >> 2, lt = lane & 3;

    uint32_t baseA = smem_u32(As), baseB = smem_u32(Bs);

    const __half* WdE = g_wd16 + (size_t)e * HID * DMODEL;

    float acc[2][8][4];
#pragma unroll
    for (int mt = 0; mt < 2; mt++)
#pragma unroll
        for (int nt = 0; nt < 8; nt++)
#pragma unroll
            for (int r = 0; r < 4; r++) acc[mt][nt][r] = 0.f;

    int arow = tid >> 2, asg = tid & 3;
    int brow = tid >> 4, bsg = tid & 15;   // B: 32 rows x 16 segs (128 halves)

    auto issue = [&](int c, int st) {
        uint32_t dA = baseA + (uint32_t)(st * A_TILE) * 2;
        uint32_t dB = baseB + (uint32_t)(st * BD_TILE) * 2;
#pragma unroll
        for (int q = 0; q < 2; q++) {
            int row = arow + q * 64;
            int gm = m0 + row;
            bool v = gm < mEnd;
            cpa16(dA + (uint32_t)(row * AST + asg * 8) * 2,
                  &g_h[(size_t)(v ? gm : m0) * HID + c * 32 + asg * 8], v);
        }
#pragma unroll
        for (int q = 0; q < 2; q++) {
            int row = brow + q * 16;
            cpa16(dB + (uint32_t)(row * BSTD + bsg * 8) * 2,
                  WdE + (size_t)(c * 32 + row) * DMODEL + n0 + bsg * 8, true);
        }
    };
    auto compute = [&](int st) {
        uint32_t sA = baseA + (uint32_t)(st * A_TILE) * 2;
        uint32_t sB = baseB + (uint32_t)(st * BD_TILE) * 2;
#pragma unroll
        for (int s = 0; s < 2; s++) {
            int k0 = s * 16;
            uint32_t a[2][4];
#pragma unroll
            for (int mt = 0; mt < 2; mt++) {
                uint32_t ad = sA + (uint32_t)(((wm * 32 + mt * 16 + (lane & 15)) * AST)
                                              + k0 + (lane >> 4) * 8) * 2;
                LDSM_X4(a[mt][0], a[mt][1], a[mt][2], a[mt][3], ad);
            }
#pragma unroll
            for (int np = 0; np < 4; np++) {
                uint32_t boff = (uint32_t)(((k0 + (lane & 15)) * BSTD)
                                           + wn * 64 + np * 16 + (lane >> 4) * 8) * 2;
                uint32_t b0, b1, b2, b3;
                LDSM_X4T(b0, b1, b2, b3, sB + boff);
#pragma unroll
                for (int mt = 0; mt < 2; mt++) {
                    MMA16816(acc[mt][np * 2 + 0], a[mt], b0, b1);
                    MMA16816(acc[mt][np * 2 + 1], a[mt], b2, b3);
                }
            }
        }
    };

    issue(0, 0); CP_COMMIT();
    issue(1, 1); CP_COMMIT();

    for (int c = 0; c < NC_DN; c++) {
        CP_WAIT1();
        __syncthreads();
        if (c + 2 < NC_DN) issue(c + 2, (c + 2) % 3);
        CP_COMMIT();
        compute(c % 3);
    }

#pragma unroll
    for (int mt = 0; mt < 2; mt++) {
#pragma unroll
        for (int nt = 0; nt < 8; nt++) {
            int row0 = m0 + wm * 32 + mt * 16 + lg;
            int col  = n0 + wn * 64 + nt * 8 + lt * 2;
            if (row0 < mEnd) {
                int token = g_tok[row0];
                float gate = g_gate[token];
                *(float2*)&out[(size_t)token * DMODEL + col] =
                    make_float2(acc[mt][nt][0] * gate, acc[mt][nt][1] * gate);
            }
            int row1 = row0 + 8;
            if (row1 < mEnd) {
                int token = g_tok[row1];
                float gate = g_gate[token];
                *(float2*)&out[(size_t)token * DMODEL + col] =
                    make_float2(acc[mt][nt][2] * gate, acc[mt][nt][3] * gate);
            }
        }
    }
}

// ---------------- aux --------------------------------------------------------
__global__ void aux_kernel(float* __restrict__ out) {
    float s = 0.f;
    for (int e = 0; e < NE; e++) {
        float me = (float)g_counts[e] / (float)T_TOK;
        float ce = g_ce[e] / (float)T_TOK;
        s += me * ce;
    }
    out[(size_t)T_TOK * DMODEL] = ALPHA * NE * s;
}

// ---------------- launch -----------------------------------------------------
extern "C" void kernel_launch(void* const* d_in, const int* in_sizes, int n_in,
                              void* d_out, int out_size) {
    const float* x   = (const float*)d_in[0];
    const float* wgw = (const float*)d_in[1];
    const float* wgb = (const float*)d_in[2];
    const float* Wu  = (const float*)d_in[3];
    const float* Wv  = (const float*)d_in[4];
    const float* Wd  = (const float*)d_in[5];
    float* out = (float*)d_out;

    cudaFuncSetAttribute(up_mma, cudaFuncAttributeMaxDynamicSharedMemorySize, UP_SMEM);
    cudaFuncSetAttribute(dn_mma, cudaFuncAttributeMaxDynamicSharedMemorySize, DN_SMEM);

    init_kernel<<<1, 32>>>();
    gate_kernel<<<GATE_BLOCKS + CONVUV_BLOCKS, 256>>>(x, wgw, wgb, Wu, Wv);
    gather_kernel<<<GATHER_BLOCKS + CONVD_BLOCKS, 192>>>(x, Wd);
    up_mma<<<dim3(HID / 64, T_TOK / 128, NE), 256, UP_SMEM>>>(nullptr);
    dn_mma<<<dim3(DMODEL / 128, T_TOK / 128, NE), 256, DN_SMEM>>>(out);
    aux_kernel<<<1, 1>>>(out);
}

// round 11
// speedup vs baseline: 1.3953x; 1.0314x over previous
#include <cuda_runtime.h>
#include <cuda_fp16.h>
#include <cstdint>

#define T_TOK 4096
#define DMODEL 768
#define HID 2048
#define NE 8
#define ALPHA 0.05f

#define AST 40                 // A smem row stride (halves)
#define BST 72                 // up B smem row stride (halves)
#define BSTD 136               // dn B smem row stride (halves), BN=128 + pad
#define NC_UP (DMODEL / 32)    // 24
#define NC_DN (HID / 32)       // 64
#define A_TILE (128 * AST)
#define B_TILE (32 * BST)
#define BD_TILE (32 * BSTD)
#define UP_SMEM ((3 * (A_TILE + 2 * B_TILE)) * 2)    // 58368 B
#define DN_SMEM ((3 * (A_TILE + BD_TILE)) * 2)       // 56832 B

#define GATE_BLOCKS 512
#define CONVUV_BLOCKS 1536
#define GATHER_BLOCKS T_TOK

// ---------------- scratch ----------------------------------------------------
__device__ int   g_expert[T_TOK];
__device__ float g_gate[T_TOK];
__device__ int   g_counts[NE];
__device__ int   g_off[NE + 1];
__device__ int   g_cursor[NE];
__device__ float g_ce[NE];
__device__ int   g_tok[T_TOK];
__device__ int   g_done;
__device__ __align__(16) __half g_xg[(size_t)T_TOK * DMODEL];
__device__ __align__(16) __half g_h[(size_t)T_TOK * HID];
__device__ __align__(16) __half g_wu16[(size_t)NE * DMODEL * HID];
__device__ __align__(16) __half g_wv16[(size_t)NE * DMODEL * HID];
__device__ __align__(16) __half g_wd16[(size_t)NE * HID * DMODEL];

// ---------------- helpers ----------------------------------------------------
__device__ __forceinline__ uint32_t smem_u32(const void* p) {
    uint32_t a;
    asm("{ .reg .u64 t; cvta.to.shared.u64 t, %1; cvt.u32.u64 %0, t; }" : "=r"(a) : "l"(p));
    return a;
}
__device__ __forceinline__ uint32_t pk(float a, float b) {
    __half2 h = __floats2half2_rn(a, b);
    return *reinterpret_cast<uint32_t*>(&h);
}
__device__ __forceinline__ void cpa16(uint32_t dst, const void* src, bool valid) {
    int sz = valid ? 16 : 0;
    asm volatile("cp.async.cg.shared.global [%0], [%1], 16, %2;\n"
                 :: "r"(dst), "l"(src), "r"(sz) : "memory");
}
#define CP_COMMIT() asm volatile("cp.async.commit_group;" ::: "memory")
#define CP_WAIT1()  asm volatile("cp.async.wait_group 1;" ::: "memory")

#define LDSM_X4(r0, r1, r2, r3, a)                                              \
    asm volatile("ldmatrix.sync.aligned.m8n8.x4.shared.b16 {%0,%1,%2,%3}, [%4];"\
                 : "=r"(r0), "=r"(r1), "=r"(r2), "=r"(r3) : "r"(a))
#define LDSM_X4T(r0, r1, r2, r3, a)                                             \
    asm volatile("ldmatrix.sync.aligned.m8n8.x4.trans.shared.b16 {%0,%1,%2,%3}, [%4];"\
                 : "=r"(r0), "=r"(r1), "=r"(r2), "=r"(r3) : "r"(a))

#define MMA16816(d, a, b0, b1)                                                  \
    asm volatile("mma.sync.aligned.m16n8k16.row.col.f32.f16.f16.f32 "           \
                 "{%0,%1,%2,%3},{%4,%5,%6,%7},{%8,%9},{%0,%1,%2,%3};"           \
                 : "+f"((d)[0]), "+f"((d)[1]), "+f"((d)[2]), "+f"((d)[3])       \
                 : "r"((a)[0]), "r"((a)[1]), "r"((a)[2]), "r"((a)[3]),          \
                   "r"(b0), "r"(b1))

// ---------------- init -------------------------------------------------------
__global__ void init_kernel() {
    int i = threadIdx.x;
    if (i < NE) { g_counts[i] = 0; g_ce[i] = 0.f; }
    if (i == 0) g_done = 0;
}

// ---------------- gate (+ Wu/Wv convert in extra blocks, + inline scan) ------
__global__ void gate_kernel(const float* __restrict__ x,
                            const float* __restrict__ wgw,
                            const float* __restrict__ wgb,
                            const float* __restrict__ Wu,
                            const float* __restrict__ Wv) {
    int tid = threadIdx.x;

    if (blockIdx.x >= GATE_BLOCKS) {
        const size_t n4 = (size_t)NE * DMODEL * HID / 4;
        size_t i0 = (size_t)(blockIdx.x - GATE_BLOCKS) * blockDim.x + tid;
        size_t stride = (size_t)CONVUV_BLOCKS * blockDim.x;
        for (size_t i = i0; i < n4; i += stride) {
            float4 a = ((const float4*)Wu)[i];
            ((uint2*)g_wu16)[i] = make_uint2(pk(a.x, a.y), pk(a.z, a.w));
            float4 b = ((const float4*)Wv)[i];
            ((uint2*)g_wv16)[i] = make_uint2(pk(b.x, b.y), pk(b.z, b.w));
        }
        return;
    }

    __shared__ float s_ce[NE];
    __shared__ int   s_cnt[NE];
    if (tid < NE) { s_ce[tid] = 0.f; s_cnt[tid] = 0; }
    __syncthreads();

    int warp = tid >> 5, lane = tid & 31;
    int t = blockIdx.x * 8 + warp;

    float acc[NE];
#pragma unroll
    for (int e = 0; e < NE; e++) acc[e] = 0.f;
    const float* xr = x + (size_t)t * DMODEL;
    for (int i = lane; i < DMODEL; i += 32) {
        float xv = xr[i];
#pragma unroll
        for (int e = 0; e < NE; e++) acc[e] += xv * wgw[e * DMODEL + i];
    }
#pragma unroll
    for (int e = 0; e < NE; e++)
#pragma unroll
        for (int o = 16; o > 0; o >>= 1) acc[e] += __shfl_xor_sync(0xFFFFFFFFu, acc[e], o);

    if (lane == 0) {
        float mx = -1e30f; int be = 0;
#pragma unroll
        for (int e = 0; e < NE; e++) {
            acc[e] += wgb[e];
            if (acc[e] > mx) { mx = acc[e]; be = e; }
        }
        float p[NE]; float s = 0.f;
#pragma unroll
        for (int e = 0; e < NE; e++) { p[e] = __expf(acc[e] - mx); s += p[e]; }
        float inv = 1.f / s;
#pragma unroll
        for (int e = 0; e < NE; e++) { p[e] *= inv; atomicAdd(&s_ce[e], p[e]); }
        g_expert[t] = be;
        g_gate[t]   = p[be];
        atomicAdd(&s_cnt[be], 1);
    }
    __syncthreads();
    if (tid < NE) { atomicAdd(&g_ce[tid], s_ce[tid]); atomicAdd(&g_counts[tid], s_cnt[tid]); }

    if (tid == 0) {
        __threadfence();
        int prev = atomicAdd(&g_done, 1);
        if (prev == GATE_BLOCKS - 1) {
            int s = 0;
            for (int e = 0; e < NE; e++) {
                int cnt = atomicAdd(&g_counts[e], 0);
                g_off[e] = s; g_cursor[e] = s; s += cnt;
            }
            g_off[NE] = s;
            __threadfence();
        }
    }
}

// ---------------- gather (convD removed — now hidden under up_mma) -----------
__global__ void gather_kernel(const float* __restrict__ x) {
    __shared__ int s_pos;
    int t = blockIdx.x;
    if (threadIdx.x == 0) {
        int e = g_expert[t];
        int pos = atomicAdd(&g_cursor[e], 1);
        g_tok[pos] = t;
        s_pos = pos;
    }
    __syncthreads();
    int pos = s_pos;
    const float4* src = (const float4*)(x + (size_t)t * DMODEL);
    __half2* dst = (__half2*)(g_xg + (size_t)pos * DMODEL);
    for (int i = threadIdx.x; i < DMODEL / 4; i += blockDim.x) {
        float4 v = src[i];
        dst[i * 2 + 0] = __floats2half2_rn(v.x, v.y);
        dst[i * 2 + 1] = __floats2half2_rn(v.z, v.w);
    }
}

// ---------------- up: H = silu(Xe@Wu)*(Xe@Wv); z==NE slice converts Wd -------
__global__ __launch_bounds__(256, 2) void up_mma(const float* __restrict__ Wd) {
    // ---- grid.z == NE: Wd fp32 -> fp16 conversion, co-running with GEMM ----
    if (blockIdx.z == NE) {
        const size_t n4 = (size_t)NE * HID * DMODEL / 4;
        int bid = blockIdx.y * gridDim.x + blockIdx.x;          // 0..1023
        size_t i0 = (size_t)bid * blockDim.x + threadIdx.x;
        size_t stride = (size_t)gridDim.x * gridDim.y * blockDim.x;
        for (size_t i = i0; i < n4; i += stride) {
            float4 c = ((const float4*)Wd)[i];
            ((uint2*)g_wd16)[i] = make_uint2(pk(c.x, c.y), pk(c.z, c.w));
        }
        return;
    }

    int e    = blockIdx.z;
    int mEnd = g_off[e + 1];
    int m0   = g_off[e] + blockIdx.y * 128;
    if (m0 >= mEnd) return;
    int n0 = blockIdx.x * 64;

    extern __shared__ __align__(16) __half smem[];
    __half* As = smem;
    __half* Bu = smem + 3 * A_TILE;
    __half* Bv = Bu + 3 * B_TILE;

    int tid = threadIdx.x, lane = tid & 31, wid = tid >> 5;
    int wm = wid & 3, wn = wid >> 2;
    int lg = lane >> 2, lt = lane & 3;

    uint32_t baseA = smem_u32(As), baseU = smem_u32(Bu), baseV = smem_u32(Bv);

    const __half* WuE = g_wu16 + (size_t)e * DMODEL * HID;
    const __half* WvE = g_wv16 + (size_t)e * DMODEL * HID;

    float au[2][4][4], av[2][4][4];
#pragma unroll
    for (int mt = 0; mt < 2; mt++)
#pragma unroll
        for (int nt = 0; nt < 4; nt++)
#pragma unroll
            for (int r = 0; r < 4; r++) { au[mt][nt][r] = 0.f; av[mt][nt][r] = 0.f; }

    int arow = tid >> 2, asg = tid & 3;
    int brow = tid >> 3, bsg = tid & 7;

    auto issue = [&](int c, int st) {
        uint32_t dA = baseA + (uint32_t)(st * A_TILE) * 2;
        uint32_t dU = baseU + (uint32_t)(st * B_TILE) * 2;
        uint32_t dV = baseV + (uint32_t)(st * B_TILE) * 2;
#pragma unroll
        for (int q = 0; q < 2; q++) {
            int row = arow + q * 64;
            int gm = m0 + row;
            bool v = gm < mEnd;
            cpa16(dA + (uint32_t)(row * AST + asg * 8) * 2,
                  &g_xg[(size_t)(v ? gm : m0) * DMODEL + c * 32 + asg * 8], v);
        }
        size_t boff = (size_t)(c * 32 + brow) * HID + n0 + bsg * 8;
        cpa16(dU + (uint32_t)(brow * BST + bsg * 8) * 2, WuE + boff, true);
        cpa16(dV + (uint32_t)(brow * BST + bsg * 8) * 2, WvE + boff, true);
    };
    auto compute = [&](int st) {
        uint32_t sA = baseA + (uint32_t)(st * A_TILE) * 2;
        uint32_t sU = baseU + (uint32_t)(st * B_TILE) * 2;
        uint32_t sV = baseV + (uint32_t)(st * B_TILE) * 2;
#pragma unroll
        for (int s = 0; s < 2; s++) {
            int k0 = s * 16;
            uint32_t a[2][4];
#pragma unroll
            for (int mt = 0; mt < 2; mt++) {
                uint32_t ad = sA + (uint32_t)(((wm * 32 + mt * 16 + (lane & 15)) * AST)
                                              + k0 + (lane >> 4) * 8) * 2;
                LDSM_X4(a[mt][0], a[mt][1], a[mt][2], a[mt][3], ad);
            }
#pragma unroll
            for (int np = 0; np < 2; np++) {
                uint32_t boff = (uint32_t)(((k0 + (lane & 15)) * BST)
                                           + wn * 32 + np * 16 + (lane >> 4) * 8) * 2;
                uint32_t u0, u1, u2, u3, v0, v1, v2, v3;
                LDSM_X4T(u0, u1, u2, u3, sU + boff);
                LDSM_X4T(v0, v1, v2, v3, sV + boff);
#pragma unroll
                for (int mt = 0; mt < 2; mt++) {
                    MMA16816(au[mt][np * 2 + 0], a[mt], u0, u1);
                    MMA16816(au[mt][np * 2 + 1], a[mt], u2, u3);
                    MMA16816(av[mt][np * 2 + 0], a[mt], v0, v1);
                    MMA16816(av[mt][np * 2 + 1], a[mt], v2, v3);
                }
            }
        }
    };

    issue(0, 0); CP_COMMIT();
    issue(1, 1); CP_COMMIT();

    for (int c = 0; c < NC_UP; c++) {
        CP_WAIT1();
        __syncthreads();
        if (c + 2 < NC_UP) issue(c + 2, (c + 2) % 3);
        CP_COMMIT();
        compute(c % 3);
    }

#pragma unroll
    for (int mt = 0; mt < 2; mt++) {
#pragma unroll
        for (int nt = 0; nt < 4; nt++) {
            int row0 = m0 + wm * 32 + mt * 16 + lg;
            int col  = n0 + wn * 32 + nt * 8 + lt * 2;
            if (row0 < mEnd) {
                float u0 = au[mt][nt][0], u1 = au[mt][nt][1];
                float h0 = u0 / (1.f + __expf(-u0)) * av[mt][nt][0];
                float h1 = u1 / (1.f + __expf(-u1)) * av[mt][nt][1];
                *(__half2*)&g_h[(size_t)row0 * HID + col] = __floats2half2_rn(h0, h1);
            }
            int row1 = row0 + 8;
            if (row1 < mEnd) {
                float u2 = au[mt][nt][2], u3 = au[mt][nt][3];
                float h2 = u2 / (1.f + __expf(-u2)) * av[mt][nt][2];
                float h3 = u3 / (1.f + __expf(-u3)) * av[mt][nt][3];
                *(__half2*)&g_h[(size_t)row1 * HID + col] = __floats2half2_rn(h2, h3);
            }
        }
    }
}

// ---------------- down: BN=128, warp tile 32x64 (+ inline aux) ---------------
__global__ __launch_bounds__(256, 2) void dn_mma(float* __restrict__ out) {
    // ---- aux scalar (always executes: placed before early-return) ----
    if (blockIdx.x == 0 && blockIdx.y == 0 && blockIdx.z == 0 && threadIdx.x == 0) {
        float s = 0.f;
        for (int e = 0; e < NE; e++) {
            float me = (float)g_counts[e] / (float)T_TOK;
            float ce = g_ce[e] / (float)T_TOK;
            s += me * ce;
        }
        out[(size_t)T_TOK * DMODEL] = ALPHA * NE * s;
    }

    int e    = blockIdx.z;
    int mEnd = g_off[e + 1];
    int m0   = g_off[e] + blockIdx.y * 128;
    if (m0 >= mEnd) return;
    int n0 = blockIdx.x * 128;

    extern __shared__ __align__(16) __half smem[];
    __half* As = smem;
    __half* Bs = smem + 3 * A_TILE;

    int tid = threadIdx.x, lane = tid & 31, wid = tid >> 5;
    int wm = wid & 3, wn = wid >> 2;
    int lg = lane >> 2, lt = lane & 3;

    uint32_t baseA = smem_u32(As), baseB = smem_u32(Bs);

    const __half* WdE = g_wd16 + (size_t)e * HID * DMODEL;

    float acc[2][8][4];
#pragma unroll
    for (int mt = 0; mt < 2; mt++)
#pragma unroll
        for (int nt = 0; nt < 8; nt++)
#pragma unroll
            for (int r = 0; r < 4; r++) acc[mt][nt][r] = 0.f;

    int arow = tid >> 2, asg = tid & 3;
    int brow = tid >> 4, bsg = tid & 15;

    auto issue = [&](int c, int st) {
        uint32_t dA = baseA + (uint32_t)(st * A_TILE) * 2;
        uint32_t dB = baseB + (uint32_t)(st * BD_TILE) * 2;
#pragma unroll
        for (int q = 0; q < 2; q++) {
            int row = arow + q * 64;
            int gm = m0 + row;
            bool v = gm < mEnd;
            cpa16(dA + (uint32_t)(row * AST + asg * 8) * 2,
                  &g_h[(size_t)(v ? gm : m0) * HID + c * 32 + asg * 8], v);
        }
#pragma unroll
        for (int q = 0; q < 2; q++) {
            int row = brow + q * 16;
            cpa16(dB + (uint32_t)(row * BSTD + bsg * 8) * 2,
                  WdE + (size_t)(c * 32 + row) * DMODEL + n0 + bsg * 8, true);
        }
    };
    auto compute = [&](int st) {
        uint32_t sA = baseA + (uint32_t)(st * A_TILE) * 2;
        uint32_t sB = baseB + (uint32_t)(st * BD_TILE) * 2;
#pragma unroll
        for (int s = 0; s < 2; s++) {
            int k0 = s * 16;
            uint32_t a[2][4];
#pragma unroll
            for (int mt = 0; mt < 2; mt++) {
                uint32_t ad = sA + (uint32_t)(((wm * 32 + mt * 16 + (lane & 15)) * AST)
                                              + k0 + (lane >> 4) * 8) * 2;
                LDSM_X4(a[mt][0], a[mt][1], a[mt][2], a[mt][3], ad);
            }
#pragma unroll
            for (int np = 0; np < 4; np++) {
                uint32_t boff = (uint32_t)(((k0 + (lane & 15)) * BSTD)
                                           + wn * 64 + np * 16 + (lane >> 4) * 8) * 2;
                uint32_t b0, b1, b2, b3;
                LDSM_X4T(b0, b1, b2, b3, sB + boff);
#pragma unroll
                for (int mt = 0; mt < 2; mt++) {
                    MMA16816(acc[mt][np * 2 + 0], a[mt], b0, b1);
                    MMA16816(acc[mt][np * 2 + 1], a[mt], b2, b3);
                }
            }
        }
    };

    issue(0, 0); CP_COMMIT();
    issue(1, 1); CP_COMMIT();

    for (int c = 0; c < NC_DN; c++) {
        CP_WAIT1();
        __syncthreads();
        if (c + 2 < NC_DN) issue(c + 2, (c + 2) % 3);
        CP_COMMIT();
        compute(c % 3);
    }

#pragma unroll
    for (int mt = 0; mt < 2; mt++) {
#pragma unroll
        for (int nt = 0; nt < 8; nt++) {
            int row0 = m0 + wm * 32 + mt * 16 + lg;
            int col  = n0 + wn * 64 + nt * 8 + lt * 2;
            if (row0 < mEnd) {
                int token = g_tok[row0];
                float gate = g_gate[token];
                *(float2*)&out[(size_t)token * DMODEL + col] =
                    make_float2(acc[mt][nt][0] * gate, acc[mt][nt][1] * gate);
            }
            int row1 = row0 + 8;
            if (row1 < mEnd) {
                int token = g_tok[row1];
                float gate = g_gate[token];
                *(float2*)&out[(size_t)token * DMODEL + col] =
                    make_float2(acc[mt][nt][2] * gate, acc[mt][nt][3] * gate);
            }
        }
    }
}

// ---------------- launch -----------------------------------------------------
extern "C" void kernel_launch(void* const* d_in, const int* in_sizes, int n_in,
                              void* d_out, int out_size) {
    const float* x   = (const float*)d_in[0];
    const float* wgw = (const float*)d_in[1];
    const float* wgb = (const float*)d_in[2];
    const float* Wu  = (const float*)d_in[3];
    const float* Wv  = (const float*)d_in[4];
    const float* Wd  = (const float*)d_in[5];
    float* out = (float*)d_out;

    cudaFuncSetAttribute(up_mma, cudaFuncAttributeMaxDynamicSharedMemorySize, UP_SMEM);
    cudaFuncSetAttribute(dn_mma, cudaFuncAttributeMaxDynamicSharedMemorySize, DN_SMEM);

    init_kernel<<<1, 32>>>();
    gate_kernel<<<GATE_BLOCKS + CONVUV_BLOCKS, 256>>>(x, wgw, wgb, Wu, Wv);
    gather_kernel<<<GATHER_BLOCKS, 192>>>(x);
    up_mma<<<dim3(HID / 64, T_TOK / 128, NE + 1), 256, UP_SMEM>>>(Wd);
    dn_mma<<<dim3(DMODEL / 128, T_TOK / 128, NE), 256, DN_SMEM>>>(out);
}